// round 7
// baseline (speedup 1.0000x reference)
#include <cuda_runtime.h>
#include <cuda_bf16.h>
#include <cstdint>

#define B_    4
#define N_    2048
#define CIN_  256
#define COUT_ 64
#define H_    8
#define ALPHA 0.2f

// ---------------- scratch (__device__ globals; no allocs allowed) -----------
__device__ __nv_bfloat16 g_hbf_hi[(size_t)B_ * H_ * N_ * COUT_];  // [bh][n][c]
__device__ __nv_bfloat16 g_hbf_lo[(size_t)B_ * H_ * N_ * COUT_];
__device__ float g_s1[B_ * H_ * N_];
__device__ float g_s2[B_ * H_ * N_];
__device__ float g_A1[B_ * H_ * N_];    // exp(s1 - M)
__device__ float g_A2[B_ * H_ * N_];    // exp(0.2 s1 - M)
__device__ float4 g_fact[B_ * H_ * N_]; // {s2, exp(s2), exp(0.2 s2), 0}
__device__ unsigned g_bits[(size_t)B_ * N_ * (N_ / 32)];          // adj bitmask

// ---------------- helpers (sm_80-era PTX only) ------------------------------
__device__ __forceinline__ uint32_t smem_u32(const void* p) {
    uint32_t a;
    asm("{ .reg .u64 t; cvta.to.shared.u64 t, %1; cvt.u32.u64 %0, t; }"
        : "=r"(a) : "l"(p));
    return a;
}
__device__ __forceinline__ uint32_t swz128(uint32_t off) {
    return off ^ ((off >> 3) & 0x70);
}
__device__ __forceinline__ void ldsm_x4(uint32_t* r, uint32_t addr) {
    asm volatile("ldmatrix.sync.aligned.m8n8.x4.shared.b16 {%0,%1,%2,%3}, [%4];"
                 : "=r"(r[0]), "=r"(r[1]), "=r"(r[2]), "=r"(r[3]) : "r"(addr));
}
__device__ __forceinline__ void ldsm_x4_t(uint32_t* r, uint32_t addr) {
    asm volatile("ldmatrix.sync.aligned.m8n8.x4.trans.shared.b16 {%0,%1,%2,%3}, [%4];"
                 : "=r"(r[0]), "=r"(r[1]), "=r"(r[2]), "=r"(r[3]) : "r"(addr));
}
__device__ __forceinline__ void mma_bf16(float* c, const uint32_t* a, const uint32_t* b) {
    asm volatile("mma.sync.aligned.m16n8k16.row.col.f32.bf16.bf16.f32 "
                 "{%0,%1,%2,%3}, {%4,%5,%6,%7}, {%8,%9}, {%0,%1,%2,%3};"
                 : "+f"(c[0]), "+f"(c[1]), "+f"(c[2]), "+f"(c[3])
                 : "r"(a[0]), "r"(a[1]), "r"(a[2]), "r"(a[3]), "r"(b[0]), "r"(b[1]));
}
__device__ __forceinline__ void cp_async16(uint32_t dst, const void* src) {
    asm volatile("cp.async.cg.shared.global [%0], [%1], 16;"
                 :: "r"(dst), "l"(src) : "memory");
}
#define CP_COMMIT() asm volatile("cp.async.commit_group;" ::: "memory")
#define CP_WAIT0()  asm volatile("cp.async.wait_group 0;" ::: "memory")

// ---------------------------------------------------------------------------
// Kernel 1: hidden = x @ W^T ; epilogue emits bf16 hi/lo AND fused s1/s2 scores
// (f32 hidden is never written to global)
// ---------------------------------------------------------------------------
__global__ void gemm_hidden(const float* __restrict__ x,
                            const float* __restrict__ Wf,
                            const float* __restrict__ av) {
    const int b  = blockIdx.z;
    const int m0 = blockIdx.x * 64;
    const int h  = blockIdx.y;               // one head per CTA column tile
    const int col0 = h * 64;
    __shared__ float As[32][68];
    __shared__ float Bs[32][68];
    __shared__ float a1s[64], a2s[64];
    __shared__ float sred[64][2];
    const int t  = threadIdx.x;
    const int tx = t & 15, ty = t >> 4;
    float acc[4][4] = {};
    const float* xb = x + (size_t)b * N_ * CIN_;

    if (t < 64) { a1s[t] = av[h * 128 + t]; a2s[t] = av[h * 128 + 64 + t]; }

    for (int k0 = 0; k0 < CIN_; k0 += 32) {
#pragma unroll
        for (int r = 0; r < 2; r++) {
            int fidx = t + r * 256;
            int row  = fidx >> 3;
            int c4   = (fidx & 7) * 4;
            float4 v = *(const float4*)&xb[(size_t)(m0 + row) * CIN_ + k0 + c4];
            As[c4 + 0][row] = v.x; As[c4 + 1][row] = v.y;
            As[c4 + 2][row] = v.z; As[c4 + 3][row] = v.w;
            float4 w = *(const float4*)&Wf[(size_t)(col0 + row) * CIN_ + k0 + c4];
            Bs[c4 + 0][row] = w.x; Bs[c4 + 1][row] = w.y;
            Bs[c4 + 2][row] = w.z; Bs[c4 + 3][row] = w.w;
        }
        __syncthreads();
#pragma unroll
        for (int kk = 0; kk < 32; kk++) {
            float4 rm = *(const float4*)&As[kk][ty * 4];
            float4 rn = *(const float4*)&Bs[kk][tx * 4];
            float am[4] = {rm.x, rm.y, rm.z, rm.w};
            float an[4] = {rn.x, rn.y, rn.z, rn.w};
#pragma unroll
            for (int i = 0; i < 4; i++)
#pragma unroll
                for (int j = 0; j < 4; j++)
                    acc[i][j] += am[i] * an[j];
        }
        __syncthreads();
    }

    const size_t base = ((size_t)(b * H_ + h) * N_);
    float s1p[4], s2p[4];
#pragma unroll
    for (int i = 0; i < 4; i++) {
        int m = m0 + ty * 4 + i;
        size_t di = (base + m) * COUT_ + tx * 4;
        __nv_bfloat16 b0 = __float2bfloat16(acc[i][0]);
        __nv_bfloat16 b1 = __float2bfloat16(acc[i][1]);
        __nv_bfloat16 b2 = __float2bfloat16(acc[i][2]);
        __nv_bfloat16 b3 = __float2bfloat16(acc[i][3]);
        __nv_bfloat162* hp = (__nv_bfloat162*)&g_hbf_hi[di];
        hp[0] = __halves2bfloat162(b0, b1);
        hp[1] = __halves2bfloat162(b2, b3);
        __nv_bfloat162* lp = (__nv_bfloat162*)&g_hbf_lo[di];
        lp[0] = __floats2bfloat162_rn(acc[i][0] - __bfloat162float(b0),
                                      acc[i][1] - __bfloat162float(b1));
        lp[1] = __floats2bfloat162_rn(acc[i][2] - __bfloat162float(b2),
                                      acc[i][3] - __bfloat162float(b3));
        // fused score partials over this thread's 4 channels
        float p1 = acc[i][0] * a1s[tx * 4 + 0] + acc[i][1] * a1s[tx * 4 + 1]
                 + acc[i][2] * a1s[tx * 4 + 2] + acc[i][3] * a1s[tx * 4 + 3];
        float p2 = acc[i][0] * a2s[tx * 4 + 0] + acc[i][1] * a2s[tx * 4 + 1]
                 + acc[i][2] * a2s[tx * 4 + 2] + acc[i][3] * a2s[tx * 4 + 3];
        s1p[i] = p1; s2p[i] = p2;
    }
    // reduce across the 16 tx lanes (lanes 0-15 / 16-31 are one ty each)
#pragma unroll
    for (int off = 8; off > 0; off >>= 1) {
#pragma unroll
        for (int i = 0; i < 4; i++) {
            s1p[i] += __shfl_xor_sync(0xffffffffu, s1p[i], off);
            s2p[i] += __shfl_xor_sync(0xffffffffu, s2p[i], off);
        }
    }
    if (tx == 0) {
#pragma unroll
        for (int i = 0; i < 4; i++) {
            sred[ty * 4 + i][0] = s1p[i];
            sred[ty * 4 + i][1] = s2p[i];
        }
    }
    __syncthreads();
    if (t < 64) {
        g_s1[base + m0 + t] = sred[t][0];
        g_s2[base + m0 + t] = sred[t][1];
    }
}

// ---------------------------------------------------------------------------
// Kernel 2: per (b,h): s2max reduce + factor precompute (A1/A2 + packed fact4)
// ---------------------------------------------------------------------------
__global__ void row_factors() {
    __shared__ float red[256];
    __shared__ float s2max_s;
    int bh = blockIdx.x;
    const float* s1 = g_s1 + bh * N_;
    const float* s2 = g_s2 + bh * N_;
    float m = -1e30f;
    for (int j = threadIdx.x; j < N_; j += 256) m = fmaxf(m, s2[j]);
    red[threadIdx.x] = m;
    __syncthreads();
    for (int s = 128; s > 0; s >>= 1) {
        if (threadIdx.x < s) red[threadIdx.x] = fmaxf(red[threadIdx.x], red[threadIdx.x + s]);
        __syncthreads();
    }
    if (threadIdx.x == 0) s2max_s = red[0];
    __syncthreads();
    const float s2m = s2max_s;
    for (int j = threadIdx.x; j < N_; j += 256) {
        float s1v = s1[j], s2v = s2[j];
        float e = s1v + s2m;
        float M = (e >= 0.f) ? e : ALPHA * e;
        g_A1[bh * N_ + j] = __expf(s1v - M);
        g_A2[bh * N_ + j] = __expf(ALPHA * s1v - M);
        g_fact[bh * N_ + j] = make_float4(s2v, __expf(s2v), __expf(ALPHA * s2v), 0.f);
    }
}

// ---------------------------------------------------------------------------
// Kernel 3: adj -> bitmask, 4 words per loop iteration (MLP 4)
// ---------------------------------------------------------------------------
__global__ void adj_bits_k(const int* __restrict__ adj) {
    int wid  = threadIdx.x >> 5, lane = threadIdx.x & 31;
    int row  = blockIdx.x * 8 + wid;                  // over B_*N_
    const int* ap = adj + (size_t)row * N_;
    unsigned* bp  = g_bits + (size_t)row * (N_ / 32);
#pragma unroll 4
    for (int w2 = 0; w2 < N_ / 128; w2++) {
        int v0 = ap[w2 * 128 + lane];
        int v1 = ap[w2 * 128 + 32 + lane];
        int v2 = ap[w2 * 128 + 64 + lane];
        int v3 = ap[w2 * 128 + 96 + lane];
        unsigned m0 = __ballot_sync(0xffffffffu, v0 > 0);
        unsigned m1 = __ballot_sync(0xffffffffu, v1 > 0);
        unsigned m2 = __ballot_sync(0xffffffffu, v2 > 0);
        unsigned m3 = __ballot_sync(0xffffffffu, v3 > 0);
        if (lane == 0) {
            bp[w2 * 4 + 0] = m0; bp[w2 * 4 + 1] = m1;
            bp[w2 * 4 + 2] = m2; bp[w2 * 4 + 3] = m3;
        }
    }
}

// ---------------------------------------------------------------------------
// Kernel 4 v6: HMMA AV; factor reads via __ldg (broadcast, L1);
// smem 48.8 KB -> 3 CTAs/SM (launch_bounds cap 85 regs).
// ---------------------------------------------------------------------------
#define OFF_AHI  0          // [128][64] bf16 SW128  16 KB
#define OFF_ALO  16384
#define OFF_BHI  32768      // [64][64]  bf16 SW128   8 KB
#define OFF_BLO  40960
#define OFF_WSUM 49152      // float[128]
#define OFF_BIAS 49664      // float[64]
#define SMEM_TOTAL 49920

__global__ void __launch_bounds__(256, 3) attn_av_mma(const float* __restrict__ bias,
                                                      float* __restrict__ out) {
    extern __shared__ char smem[];
    const uint32_t sb = smem_u32(smem);
    const int b = blockIdx.z, h = blockIdx.y, i0 = blockIdx.x * 128;
    const int bh = b * H_ + h;
    const int t = threadIdx.x, wid = t >> 5, lane = t & 31;

    float* wsum_s = (float*)(smem + OFF_WSUM);
    float* bias_s = (float*)(smem + OFF_BIAS);
    if (t < 16) *(float4*)&bias_s[t * 4] = *(const float4*)&bias[h * COUT_ + t * 4];

    // weight-phase identity: thread -> row wrow, half whalf (32 j's)
    const int wrow = t >> 1, whalf = t & 1;
    const float s1i = g_s1[bh * N_ + i0 + wrow];
    const float A1  = g_A1[bh * N_ + i0 + wrow];
    const float A2  = g_A2[bh * N_ + i0 + wrow];
    float rowsum = 0.f;

    const __nv_bfloat16* hHi = g_hbf_hi + (size_t)bh * N_ * COUT_;
    const __nv_bfloat16* hLo = g_hbf_lo + (size_t)bh * N_ * COUT_;
    const float4* factb = g_fact + (size_t)bh * N_;
    const unsigned* bitsb = g_bits + ((size_t)(b * N_ + i0)) * (N_ / 32);
    unsigned wordv = bitsb[(size_t)wrow * (N_ / 32) + whalf];

    // ldmatrix lane addressing
    const int m0 = wid * 16;
    const int lrow = (lane & 7) + ((lane >> 3) & 1) * 8;
    const int lcol = (lane & 16) ? 16 : 0;
    const uint32_t aRowByte = (uint32_t)(m0 + lrow) * 128 + lcol;

    float acc[8][4] = {};

    for (int jt = 0; jt < 32; jt++) {
        const int j0 = jt * 64;
        __syncthreads();   // prior MMA consumed tiles

        // ---- B tiles via cp.async (overlaps with weight phase) ----
#pragma unroll
        for (int r = 0; r < 2; r++) {
            int idx = t + r * 256;
            int row = idx >> 3, ch = idx & 7;
            const size_t gsrc = (size_t)(j0 + row) * COUT_ + ch * 8;
            uint32_t so = swz128(row * 128 + ch * 16);
            cp_async16(sb + OFF_BHI + so, hHi + gsrc);
            cp_async16(sb + OFF_BLO + so, hLo + gsrc);
        }
        CP_COMMIT();

        // ---- weight phase: factorized exp, truncation hi/lo split ----
        {
            const int jb = j0 + whalf * 32;
            float lsum = 0.f;
#pragma unroll
            for (int c = 0; c < 4; c++) {
                uint32_t pk[4], pl[4];
#pragma unroll
                for (int u = 0; u < 4; u++) {
                    int k0 = c * 8 + u * 2;
                    float4 f0 = __ldg(&factb[jb + k0]);
                    float4 f1 = __ldg(&factb[jb + k0 + 1]);
                    bool p0 = (s1i + f0.x) >= 0.f;
                    bool p1 = (s1i + f1.x) >= 0.f;
                    float w0 = (p0 ? A1 : A2) * (p0 ? f0.y : f0.z);
                    float w1 = (p1 ? A1 : A2) * (p1 ? f1.y : f1.z);
                    w0 = ((wordv >> k0) & 1u) ? w0 : 0.f;
                    w1 = ((wordv >> (k0 + 1)) & 1u) ? w1 : 0.f;
                    lsum += w0 + w1;
                    uint32_t u0 = __float_as_uint(w0), u1 = __float_as_uint(w1);
                    uint32_t h0 = u0 & 0xFFFF0000u, h1 = u1 & 0xFFFF0000u;
                    pk[u] = __byte_perm(h0, h1, 0x7632);   // {bf16(w1),bf16(w0)}
                    float l0 = w0 - __uint_as_float(h0);
                    float l1 = w1 - __uint_as_float(h1);
                    __nv_bfloat162 lq = __floats2bfloat162_rn(l0, l1);
                    pl[u] = *(uint32_t*)&lq;
                }
                uint32_t so = swz128(wrow * 128 + whalf * 64 + c * 16);
                *(uint4*)(smem + OFF_AHI + so) = make_uint4(pk[0], pk[1], pk[2], pk[3]);
                *(uint4*)(smem + OFF_ALO + so) = make_uint4(pl[0], pl[1], pl[2], pl[3]);
            }
            lsum += __shfl_xor_sync(0xffffffffu, lsum, 1);
            if (whalf == 0) rowsum += lsum;
        }

        // prefetch next adj word (latency hidden by MMA phase)
        unsigned word_next = (jt < 31)
            ? bitsb[(size_t)wrow * (N_ / 32) + (jt + 1) * 2 + whalf] : 0u;

        CP_WAIT0();
        __syncthreads();   // A + B tiles ready

        // ---- MMA: 4 ksteps x 4 q x 2 s x 3 split terms ----
#pragma unroll
        for (int ks = 0; ks < 4; ks++) {
            uint32_t ah[4], al[4];
            ldsm_x4(ah, sb + OFF_AHI + swz128(aRowByte + ks * 32));
            ldsm_x4(al, sb + OFF_ALO + swz128(aRowByte + ks * 32));
#pragma unroll
            for (int q = 0; q < 4; q++) {
                uint32_t bhf[4], blf[4];
                uint32_t boff = swz128((uint32_t)(ks * 16 + lrow) * 128 + q * 32 + lcol);
                ldsm_x4_t(bhf, sb + OFF_BHI + boff);
                ldsm_x4_t(blf, sb + OFF_BLO + boff);
#pragma unroll
                for (int s = 0; s < 2; s++) {
                    int nt = q * 2 + s;
                    mma_bf16(acc[nt], ah, &bhf[s * 2]);
                    mma_bf16(acc[nt], ah, &blf[s * 2]);
                    mma_bf16(acc[nt], al, &bhf[s * 2]);
                }
            }
        }
        wordv = word_next;
    }

    if (whalf == 0) wsum_s[wrow] = rowsum;
    __syncthreads();

    // ---- epilogue ----
    const int r0 = m0 + (lane >> 2);
    const int r1 = r0 + 8;
    const float inv0 = 1.f / wsum_s[r0];
    const float inv1 = 1.f / wsum_s[r1];
    float* op0 = out + ((size_t)(b * N_ + i0 + r0)) * (H_ * COUT_) + h * COUT_;
    float* op1 = out + ((size_t)(b * N_ + i0 + r1)) * (H_ * COUT_) + h * COUT_;
#pragma unroll
    for (int nt = 0; nt < 8; nt++) {
        int col = nt * 8 + (lane & 3) * 2;
        float bx = bias_s[col], by = bias_s[col + 1];
        float2 o0, o1;
        o0.x = fmaxf(acc[nt][0] * inv0 + bx, 0.f);
        o0.y = fmaxf(acc[nt][1] * inv0 + by, 0.f);
        o1.x = fmaxf(acc[nt][2] * inv1 + bx, 0.f);
        o1.y = fmaxf(acc[nt][3] * inv1 + by, 0.f);
        *(float2*)&op0[col] = o0;
        *(float2*)&op1[col] = o1;
    }
}

// ---------------------------------------------------------------------------
extern "C" void kernel_launch(void* const* d_in, const int* in_sizes, int n_in,
                              void* d_out, int out_size) {
    const float* x    = (const float*)d_in[0];
    const int*   adj  = (const int*)  d_in[1];
    const float* W    = (const float*)d_in[2];
    const float* a    = (const float*)d_in[3];
    const float* bias = (const float*)d_in[4];
    float* out = (float*)d_out;

    cudaFuncSetAttribute(attn_av_mma, cudaFuncAttributeMaxDynamicSharedMemorySize,
                         SMEM_TOTAL);

    adj_bits_k<<<(B_ * N_) / 8, 256>>>(adj);

    dim3 g1(N_ / 64, H_, B_);
    gemm_hidden<<<g1, 256>>>(x, W, a);

    row_factors<<<B_ * H_, 256>>>();

    dim3 g4(N_ / 128, H_, B_);
    attn_av_mma<<<g4, 256, SMEM_TOTAL>>>(bias, out);
}

// round 8
// speedup vs baseline: 1.4024x; 1.4024x over previous
#include <cuda_runtime.h>
#include <cuda_bf16.h>
#include <cstdint>

#define B_    4
#define N_    2048
#define CIN_  256
#define COUT_ 64
#define H_    8
#define ALPHA 0.2f

// ---------------- scratch (__device__ globals; no allocs allowed) -----------
__device__ __nv_bfloat16 g_hbf_hi[(size_t)B_ * H_ * N_ * COUT_];  // [bh][n][c]
__device__ __nv_bfloat16 g_hbf_lo[(size_t)B_ * H_ * N_ * COUT_];
__device__ float g_s1[B_ * H_ * N_];
__device__ float g_s2[B_ * H_ * N_];
__device__ float g_A1[B_ * H_ * N_];    // exp(s1 - M)
__device__ float g_A2[B_ * H_ * N_];    // exp(0.2 s1 - M)
__device__ float g_B1[B_ * H_ * N_];    // exp(s2)
__device__ float g_B2[B_ * H_ * N_];    // exp(0.2 s2)
__device__ unsigned g_bits[(size_t)B_ * N_ * (N_ / 32)];          // adj bitmask

// ---------------- helpers (sm_80-era PTX only) ------------------------------
__device__ __forceinline__ uint32_t smem_u32(const void* p) {
    uint32_t a;
    asm("{ .reg .u64 t; cvta.to.shared.u64 t, %1; cvt.u32.u64 %0, t; }"
        : "=r"(a) : "l"(p));
    return a;
}
__device__ __forceinline__ uint32_t swz128(uint32_t off) {
    return off ^ ((off >> 3) & 0x70);
}
__device__ __forceinline__ void ldsm_x4(uint32_t* r, uint32_t addr) {
    asm volatile("ldmatrix.sync.aligned.m8n8.x4.shared.b16 {%0,%1,%2,%3}, [%4];"
                 : "=r"(r[0]), "=r"(r[1]), "=r"(r[2]), "=r"(r[3]) : "r"(addr));
}
__device__ __forceinline__ void ldsm_x4_t(uint32_t* r, uint32_t addr) {
    asm volatile("ldmatrix.sync.aligned.m8n8.x4.trans.shared.b16 {%0,%1,%2,%3}, [%4];"
                 : "=r"(r[0]), "=r"(r[1]), "=r"(r[2]), "=r"(r[3]) : "r"(addr));
}
__device__ __forceinline__ void mma_bf16(float* c, const uint32_t* a, const uint32_t* b) {
    asm volatile("mma.sync.aligned.m16n8k16.row.col.f32.bf16.bf16.f32 "
                 "{%0,%1,%2,%3}, {%4,%5,%6,%7}, {%8,%9}, {%0,%1,%2,%3};"
                 : "+f"(c[0]), "+f"(c[1]), "+f"(c[2]), "+f"(c[3])
                 : "r"(a[0]), "r"(a[1]), "r"(a[2]), "r"(a[3]), "r"(b[0]), "r"(b[1]));
}
__device__ __forceinline__ void cp_async16(uint32_t dst, const void* src) {
    asm volatile("cp.async.cg.shared.global [%0], [%1], 16;"
                 :: "r"(dst), "l"(src) : "memory");
}
#define CP_COMMIT() asm volatile("cp.async.commit_group;" ::: "memory")
#define CP_WAIT0()  asm volatile("cp.async.wait_group 0;" ::: "memory")

// ---------------------------------------------------------------------------
// Kernel 1: hidden = x @ W^T ; epilogue emits bf16 hi/lo AND fused s1/s2 scores
// (f32 hidden never touches global memory)
// ---------------------------------------------------------------------------
__global__ void gemm_hidden(const float* __restrict__ x,
                            const float* __restrict__ Wf,
                            const float* __restrict__ av) {
    const int b  = blockIdx.z;
    const int m0 = blockIdx.x * 64;
    const int h  = blockIdx.y;
    const int col0 = h * 64;
    __shared__ float As[32][68];
    __shared__ float Bs[32][68];
    __shared__ float a1s[64], a2s[64];
    __shared__ float sred[64][2];
    const int t  = threadIdx.x;
    const int tx = t & 15, ty = t >> 4;
    float acc[4][4] = {};
    const float* xb = x + (size_t)b * N_ * CIN_;

    if (t < 64) { a1s[t] = av[h * 128 + t]; a2s[t] = av[h * 128 + 64 + t]; }

    for (int k0 = 0; k0 < CIN_; k0 += 32) {
#pragma unroll
        for (int r = 0; r < 2; r++) {
            int fidx = t + r * 256;
            int row  = fidx >> 3;
            int c4   = (fidx & 7) * 4;
            float4 v = *(const float4*)&xb[(size_t)(m0 + row) * CIN_ + k0 + c4];
            As[c4 + 0][row] = v.x; As[c4 + 1][row] = v.y;
            As[c4 + 2][row] = v.z; As[c4 + 3][row] = v.w;
            float4 w = *(const float4*)&Wf[(size_t)(col0 + row) * CIN_ + k0 + c4];
            Bs[c4 + 0][row] = w.x; Bs[c4 + 1][row] = w.y;
            Bs[c4 + 2][row] = w.z; Bs[c4 + 3][row] = w.w;
        }
        __syncthreads();
#pragma unroll
        for (int kk = 0; kk < 32; kk++) {
            float4 rm = *(const float4*)&As[kk][ty * 4];
            float4 rn = *(const float4*)&Bs[kk][tx * 4];
            float am[4] = {rm.x, rm.y, rm.z, rm.w};
            float an[4] = {rn.x, rn.y, rn.z, rn.w};
#pragma unroll
            for (int i = 0; i < 4; i++)
#pragma unroll
                for (int j = 0; j < 4; j++)
                    acc[i][j] += am[i] * an[j];
        }
        __syncthreads();
    }

    const size_t base = ((size_t)(b * H_ + h) * N_);
    float s1p[4], s2p[4];
#pragma unroll
    for (int i = 0; i < 4; i++) {
        int m = m0 + ty * 4 + i;
        size_t di = (base + m) * COUT_ + tx * 4;
        __nv_bfloat16 b0 = __float2bfloat16(acc[i][0]);
        __nv_bfloat16 b1 = __float2bfloat16(acc[i][1]);
        __nv_bfloat16 b2 = __float2bfloat16(acc[i][2]);
        __nv_bfloat16 b3 = __float2bfloat16(acc[i][3]);
        __nv_bfloat162* hp = (__nv_bfloat162*)&g_hbf_hi[di];
        hp[0] = __halves2bfloat162(b0, b1);
        hp[1] = __halves2bfloat162(b2, b3);
        __nv_bfloat162* lp = (__nv_bfloat162*)&g_hbf_lo[di];
        lp[0] = __floats2bfloat162_rn(acc[i][0] - __bfloat162float(b0),
                                      acc[i][1] - __bfloat162float(b1));
        lp[1] = __floats2bfloat162_rn(acc[i][2] - __bfloat162float(b2),
                                      acc[i][3] - __bfloat162float(b3));
        float p1 = acc[i][0] * a1s[tx * 4 + 0] + acc[i][1] * a1s[tx * 4 + 1]
                 + acc[i][2] * a1s[tx * 4 + 2] + acc[i][3] * a1s[tx * 4 + 3];
        float p2 = acc[i][0] * a2s[tx * 4 + 0] + acc[i][1] * a2s[tx * 4 + 1]
                 + acc[i][2] * a2s[tx * 4 + 2] + acc[i][3] * a2s[tx * 4 + 3];
        s1p[i] = p1; s2p[i] = p2;
    }
#pragma unroll
    for (int off = 8; off > 0; off >>= 1) {
#pragma unroll
        for (int i = 0; i < 4; i++) {
            s1p[i] += __shfl_xor_sync(0xffffffffu, s1p[i], off);
            s2p[i] += __shfl_xor_sync(0xffffffffu, s2p[i], off);
        }
    }
    if (tx == 0) {
#pragma unroll
        for (int i = 0; i < 4; i++) {
            sred[ty * 4 + i][0] = s1p[i];
            sred[ty * 4 + i][1] = s2p[i];
        }
    }
    __syncthreads();
    if (t < 64) {
        g_s1[base + m0 + t] = sred[t][0];
        g_s2[base + m0 + t] = sred[t][1];
    }
}

// ---------------------------------------------------------------------------
// Kernel 2: per (b,h): s2max reduce + factor precompute
// ---------------------------------------------------------------------------
__global__ void row_factors() {
    __shared__ float red[256];
    __shared__ float s2max_s;
    int bh = blockIdx.x;
    const float* s1 = g_s1 + bh * N_;
    const float* s2 = g_s2 + bh * N_;
    float m = -1e30f;
    for (int j = threadIdx.x; j < N_; j += 256) m = fmaxf(m, s2[j]);
    red[threadIdx.x] = m;
    __syncthreads();
    for (int s = 128; s > 0; s >>= 1) {
        if (threadIdx.x < s) red[threadIdx.x] = fmaxf(red[threadIdx.x], red[threadIdx.x + s]);
        __syncthreads();
    }
    if (threadIdx.x == 0) s2max_s = red[0];
    __syncthreads();
    const float s2m = s2max_s;
    for (int j = threadIdx.x; j < N_; j += 256) {
        float s1v = s1[j], s2v = s2[j];
        float e = s1v + s2m;
        float M = (e >= 0.f) ? e : ALPHA * e;
        g_A1[bh * N_ + j] = __expf(s1v - M);
        g_A2[bh * N_ + j] = __expf(ALPHA * s1v - M);
        g_B1[bh * N_ + j] = __expf(s2v);
        g_B2[bh * N_ + j] = __expf(ALPHA * s2v);
    }
}

// ---------------------------------------------------------------------------
// Kernel 3: adj -> bitmask, 4 words per loop iteration (MLP 4)
// ---------------------------------------------------------------------------
__global__ void adj_bits_k(const int* __restrict__ adj) {
    int wid  = threadIdx.x >> 5, lane = threadIdx.x & 31;
    int row  = blockIdx.x * 8 + wid;
    const int* ap = adj + (size_t)row * N_;
    unsigned* bp  = g_bits + (size_t)row * (N_ / 32);
#pragma unroll 4
    for (int w2 = 0; w2 < N_ / 128; w2++) {
        int v0 = ap[w2 * 128 + lane];
        int v1 = ap[w2 * 128 + 32 + lane];
        int v2 = ap[w2 * 128 + 64 + lane];
        int v3 = ap[w2 * 128 + 96 + lane];
        unsigned m0 = __ballot_sync(0xffffffffu, v0 > 0);
        unsigned m1 = __ballot_sync(0xffffffffu, v1 > 0);
        unsigned m2 = __ballot_sync(0xffffffffu, v2 > 0);
        unsigned m3 = __ballot_sync(0xffffffffu, v3 > 0);
        if (lane == 0) {
            bp[w2 * 4 + 0] = m0; bp[w2 * 4 + 1] = m1;
            bp[w2 * 4 + 2] = m2; bp[w2 * 4 + 3] = m3;
        }
    }
}

// ---------------------------------------------------------------------------
// Kernel 4 (round-6 proven config): HMMA AV, smem-staged factors, cp.async B.
// CTA = 128 query rows x (b,h); 8 warps. No occupancy cap (natural regs).
// ---------------------------------------------------------------------------
#define OFF_AHI  0          // [128][64] bf16 SW128  16 KB
#define OFF_ALO  16384
#define OFF_BHI  32768      // [64][64]  bf16 SW128   8 KB
#define OFF_BLO  40960
#define OFF_S2F  49152      // float[2048]            8 KB
#define OFF_B1F  57344      // float[2048]            8 KB
#define OFF_B2F  65536      // float[2048]            8 KB
#define OFF_WSUM 73728      // float[128]
#define OFF_BIAS 74240      // float[64]
#define SMEM_TOTAL 74752

__global__ void __launch_bounds__(256) attn_av_mma(const float* __restrict__ bias,
                                                   float* __restrict__ out) {
    extern __shared__ char smem[];
    const uint32_t sb = smem_u32(smem);
    const int b = blockIdx.z, h = blockIdx.y, i0 = blockIdx.x * 128;
    const int bh = b * H_ + h;
    const int t = threadIdx.x, wid = t >> 5, lane = t & 31;

    float* wsum_s = (float*)(smem + OFF_WSUM);
    float* s2f    = (float*)(smem + OFF_S2F);
    float* b1f    = (float*)(smem + OFF_B1F);
    float* b2f    = (float*)(smem + OFF_B2F);
    float* bias_s = (float*)(smem + OFF_BIAS);
    if (t < 16) *(float4*)&bias_s[t * 4] = *(const float4*)&bias[h * COUT_ + t * 4];

    // prologue: stage full per-j factor arrays (2048 each)
    {
        const float* s2g = g_s2 + bh * N_;
        const float* B1g = g_B1 + bh * N_;
        const float* B2g = g_B2 + bh * N_;
#pragma unroll
        for (int r = 0; r < 2; r++) {
            int q = (t + r * 256) * 4;
            *(float4*)&s2f[q] = *(const float4*)&s2g[q];
            *(float4*)&b1f[q] = *(const float4*)&B1g[q];
            *(float4*)&b2f[q] = *(const float4*)&B2g[q];
        }
    }

    const int wrow = t >> 1, whalf = t & 1;
    const float s1i = g_s1[bh * N_ + i0 + wrow];
    const float A1  = g_A1[bh * N_ + i0 + wrow];
    const float A2  = g_A2[bh * N_ + i0 + wrow];
    float rowsum = 0.f;

    const __nv_bfloat16* hHi = g_hbf_hi + (size_t)bh * N_ * COUT_;
    const __nv_bfloat16* hLo = g_hbf_lo + (size_t)bh * N_ * COUT_;
    const unsigned* bitsb = g_bits + ((size_t)(b * N_ + i0)) * (N_ / 32);
    unsigned wordv = bitsb[(size_t)wrow * (N_ / 32) + whalf];

    const int m0 = wid * 16;
    const int lrow = (lane & 7) + ((lane >> 3) & 1) * 8;
    const int lcol = (lane & 16) ? 16 : 0;
    const uint32_t aRowByte = (uint32_t)(m0 + lrow) * 128 + lcol;

    float acc[8][4] = {};

    for (int jt = 0; jt < 32; jt++) {
        const int j0 = jt * 64;
        __syncthreads();

        // ---- B tiles via cp.async (overlaps with weight phase) ----
#pragma unroll
        for (int r = 0; r < 2; r++) {
            int idx = t + r * 256;
            int row = idx >> 3, ch = idx & 7;
            const size_t gsrc = (size_t)(j0 + row) * COUT_ + ch * 8;
            uint32_t so = swz128(row * 128 + ch * 16);
            cp_async16(sb + OFF_BHI + so, hHi + gsrc);
            cp_async16(sb + OFF_BLO + so, hLo + gsrc);
        }
        CP_COMMIT();

        // ---- weight phase: factorized exp (smem reads), trunc hi/lo split ----
        {
            const int jb = j0 + whalf * 32;
            float lsum = 0.f;
#pragma unroll
            for (int c = 0; c < 4; c++) {
                uint32_t pk[4], pl[4];
#pragma unroll
                for (int u = 0; u < 4; u++) {
                    int k0 = c * 8 + u * 2;
                    float s2v0 = s2f[jb + k0],     f10 = b1f[jb + k0],     f20 = b2f[jb + k0];
                    float s2v1 = s2f[jb + k0 + 1], f11 = b1f[jb + k0 + 1], f21 = b2f[jb + k0 + 1];
                    bool p0 = (s1i + s2v0) >= 0.f;
                    bool p1 = (s1i + s2v1) >= 0.f;
                    float w0 = (p0 ? A1 : A2) * (p0 ? f10 : f20);
                    float w1 = (p1 ? A1 : A2) * (p1 ? f11 : f21);
                    w0 = ((wordv >> k0) & 1u) ? w0 : 0.f;
                    w1 = ((wordv >> (k0 + 1)) & 1u) ? w1 : 0.f;
                    lsum += w0 + w1;
                    uint32_t u0 = __float_as_uint(w0), u1 = __float_as_uint(w1);
                    uint32_t h0 = u0 & 0xFFFF0000u, h1 = u1 & 0xFFFF0000u;
                    pk[u] = __byte_perm(h0, h1, 0x7632);   // {bf16(w1),bf16(w0)}
                    float l0 = w0 - __uint_as_float(h0);
                    float l1 = w1 - __uint_as_float(h1);
                    __nv_bfloat162 lq = __floats2bfloat162_rn(l0, l1);
                    pl[u] = *(uint32_t*)&lq;
                }
                uint32_t so = swz128(wrow * 128 + whalf * 64 + c * 16);
                *(uint4*)(smem + OFF_AHI + so) = make_uint4(pk[0], pk[1], pk[2], pk[3]);
                *(uint4*)(smem + OFF_ALO + so) = make_uint4(pl[0], pl[1], pl[2], pl[3]);
            }
            lsum += __shfl_xor_sync(0xffffffffu, lsum, 1);
            if (whalf == 0) rowsum += lsum;
        }

        unsigned word_next = (jt < 31)
            ? bitsb[(size_t)wrow * (N_ / 32) + (jt + 1) * 2 + whalf] : 0u;

        CP_WAIT0();
        __syncthreads();

        // ---- MMA: 4 ksteps x 4 q x 2 s x 3 split terms ----
#pragma unroll
        for (int ks = 0; ks < 4; ks++) {
            uint32_t ah[4], al[4];
            ldsm_x4(ah, sb + OFF_AHI + swz128(aRowByte + ks * 32));
            ldsm_x4(al, sb + OFF_ALO + swz128(aRowByte + ks * 32));
#pragma unroll
            for (int q = 0; q < 4; q++) {
                uint32_t bhf[4], blf[4];
                uint32_t boff = swz128((uint32_t)(ks * 16 + lrow) * 128 + q * 32 + lcol);
                ldsm_x4_t(bhf, sb + OFF_BHI + boff);
                ldsm_x4_t(blf, sb + OFF_BLO + boff);
#pragma unroll
                for (int s = 0; s < 2; s++) {
                    int nt = q * 2 + s;
                    mma_bf16(acc[nt], ah, &bhf[s * 2]);
                    mma_bf16(acc[nt], ah, &blf[s * 2]);
                    mma_bf16(acc[nt], al, &bhf[s * 2]);
                }
            }
        }
        wordv = word_next;
    }

    if (whalf == 0) wsum_s[wrow] = rowsum;
    __syncthreads();

    // ---- epilogue ----
    const int r0 = m0 + (lane >> 2);
    const int r1 = r0 + 8;
    const float inv0 = 1.f / wsum_s[r0];
    const float inv1 = 1.f / wsum_s[r1];
    float* op0 = out + ((size_t)(b * N_ + i0 + r0)) * (H_ * COUT_) + h * COUT_;
    float* op1 = out + ((size_t)(b * N_ + i0 + r1)) * (H_ * COUT_) + h * COUT_;
#pragma unroll
    for (int nt = 0; nt < 8; nt++) {
        int col = nt * 8 + (lane & 3) * 2;
        float bx = bias_s[col], by = bias_s[col + 1];
        float2 o0, o1;
        o0.x = fmaxf(acc[nt][0] * inv0 + bx, 0.f);
        o0.y = fmaxf(acc[nt][1] * inv0 + by, 0.f);
        o1.x = fmaxf(acc[nt][2] * inv1 + bx, 0.f);
        o1.y = fmaxf(acc[nt][3] * inv1 + by, 0.f);
        *(float2*)&op0[col] = o0;
        *(float2*)&op1[col] = o1;
    }
}

// ---------------------------------------------------------------------------
extern "C" void kernel_launch(void* const* d_in, const int* in_sizes, int n_in,
                              void* d_out, int out_size) {
    const float* x    = (const float*)d_in[0];
    const int*   adj  = (const int*)  d_in[1];
    const float* W    = (const float*)d_in[2];
    const float* a    = (const float*)d_in[3];
    const float* bias = (const float*)d_in[4];
    float* out = (float*)d_out;

    cudaFuncSetAttribute(attn_av_mma, cudaFuncAttributeMaxDynamicSharedMemorySize,
                         SMEM_TOTAL);

    adj_bits_k<<<(B_ * N_) / 8, 256>>>(adj);

    dim3 g1(N_ / 64, H_, B_);
    gemm_hidden<<<g1, 256>>>(x, W, a);

    row_factors<<<B_ * H_, 256>>>();

    dim3 g4(N_ / 128, H_, B_);
    attn_av_mma<<<g4, 256, SMEM_TOTAL>>>(bias, out);
}

// round 9
// speedup vs baseline: 1.5334x; 1.0934x over previous
#include <cuda_runtime.h>
#include <cuda_bf16.h>
#include <cstdint>

#define B_    4
#define N_    2048
#define CIN_  256
#define COUT_ 64
#define H_    8
#define ALPHA 0.2f

// ---------------- scratch (__device__ globals; no allocs allowed) -----------
__device__ __nv_bfloat16 g_hbf_hi[(size_t)B_ * H_ * N_ * COUT_];  // [bh][n][c]
__device__ __nv_bfloat16 g_hbf_lo[(size_t)B_ * H_ * N_ * COUT_];
__device__ float g_s1[B_ * H_ * N_];
__device__ float g_s2[B_ * H_ * N_];
__device__ float g_A1[B_ * H_ * N_];    // exp(s1 - M)
__device__ float g_A2[B_ * H_ * N_];    // exp(0.2 s1 - M)
__device__ float g_B1[B_ * H_ * N_];    // exp(s2)
__device__ float g_B2[B_ * H_ * N_];    // exp(0.2 s2)
__device__ unsigned g_bits[(size_t)B_ * N_ * (N_ / 32)];          // adj bitmask

// ---------------- helpers (sm_80-era PTX only) ------------------------------
__device__ __forceinline__ uint32_t smem_u32(const void* p) {
    uint32_t a;
    asm("{ .reg .u64 t; cvta.to.shared.u64 t, %1; cvt.u32.u64 %0, t; }"
        : "=r"(a) : "l"(p));
    return a;
}
__device__ __forceinline__ uint32_t swz128(uint32_t off) {
    return off ^ ((off >> 3) & 0x70);
}
__device__ __forceinline__ void ldsm_x4_t(uint32_t* r, uint32_t addr) {
    asm volatile("ldmatrix.sync.aligned.m8n8.x4.trans.shared.b16 {%0,%1,%2,%3}, [%4];"
                 : "=r"(r[0]), "=r"(r[1]), "=r"(r[2]), "=r"(r[3]) : "r"(addr));
}
__device__ __forceinline__ void mma_bf16(float* c, const uint32_t* a, const uint32_t* b) {
    asm volatile("mma.sync.aligned.m16n8k16.row.col.f32.bf16.bf16.f32 "
                 "{%0,%1,%2,%3}, {%4,%5,%6,%7}, {%8,%9}, {%0,%1,%2,%3};"
                 : "+f"(c[0]), "+f"(c[1]), "+f"(c[2]), "+f"(c[3])
                 : "r"(a[0]), "r"(a[1]), "r"(a[2]), "r"(a[3]), "r"(b[0]), "r"(b[1]));
}
__device__ __forceinline__ void cp_async16(uint32_t dst, const void* src) {
    asm volatile("cp.async.cg.shared.global [%0], [%1], 16;"
                 :: "r"(dst), "l"(src) : "memory");
}
#define CP_COMMIT() asm volatile("cp.async.commit_group;" ::: "memory")
#define CP_WAIT0()  asm volatile("cp.async.wait_group 0;" ::: "memory")

// weight evaluation: factorized exp, no MUFU
__device__ __forceinline__ float wfun(float s1, float A1, float A2,
                                      float s2, float f1, float f2, unsigned bit) {
    float e = s1 + s2;
    float w = ((e >= 0.f) ? A1 : A2) * ((e >= 0.f) ? f1 : f2);
    return bit ? w : 0.f;
}
// truncation hi/lo split of two weights -> packed bf16x2 hi + bf16x2 lo
__device__ __forceinline__ void pack_hl(float x, float y, uint32_t& hi, uint32_t& lo) {
    uint32_t u0 = __float_as_uint(x), u1 = __float_as_uint(y);
    uint32_t h0 = u0 & 0xFFFF0000u, h1 = u1 & 0xFFFF0000u;
    hi = __byte_perm(h0, h1, 0x7632);                 // {bf16(y), bf16(x)}
    float l0 = x - __uint_as_float(h0);
    float l1 = y - __uint_as_float(h1);
    __nv_bfloat162 lq = __floats2bfloat162_rn(l0, l1);
    lo = *(uint32_t*)&lq;
}

// ---------------------------------------------------------------------------
// Kernel 1: hidden = x @ W^T ; epilogue emits bf16 hi/lo AND fused s1/s2 scores
// ---------------------------------------------------------------------------
__global__ void gemm_hidden(const float* __restrict__ x,
                            const float* __restrict__ Wf,
                            const float* __restrict__ av) {
    const int b  = blockIdx.z;
    const int m0 = blockIdx.x * 64;
    const int h  = blockIdx.y;
    const int col0 = h * 64;
    __shared__ float As[32][68];
    __shared__ float Bs[32][68];
    __shared__ float a1s[64], a2s[64];
    __shared__ float sred[64][2];
    const int t  = threadIdx.x;
    const int tx = t & 15, ty = t >> 4;
    float acc[4][4] = {};
    const float* xb = x + (size_t)b * N_ * CIN_;

    if (t < 64) { a1s[t] = av[h * 128 + t]; a2s[t] = av[h * 128 + 64 + t]; }

    for (int k0 = 0; k0 < CIN_; k0 += 32) {
#pragma unroll
        for (int r = 0; r < 2; r++) {
            int fidx = t + r * 256;
            int row  = fidx >> 3;
            int c4   = (fidx & 7) * 4;
            float4 v = *(const float4*)&xb[(size_t)(m0 + row) * CIN_ + k0 + c4];
            As[c4 + 0][row] = v.x; As[c4 + 1][row] = v.y;
            As[c4 + 2][row] = v.z; As[c4 + 3][row] = v.w;
            float4 w = *(const float4*)&Wf[(size_t)(col0 + row) * CIN_ + k0 + c4];
            Bs[c4 + 0][row] = w.x; Bs[c4 + 1][row] = w.y;
            Bs[c4 + 2][row] = w.z; Bs[c4 + 3][row] = w.w;
        }
        __syncthreads();
#pragma unroll
        for (int kk = 0; kk < 32; kk++) {
            float4 rm = *(const float4*)&As[kk][ty * 4];
            float4 rn = *(const float4*)&Bs[kk][tx * 4];
            float am[4] = {rm.x, rm.y, rm.z, rm.w};
            float an[4] = {rn.x, rn.y, rn.z, rn.w};
#pragma unroll
            for (int i = 0; i < 4; i++)
#pragma unroll
                for (int j = 0; j < 4; j++)
                    acc[i][j] += am[i] * an[j];
        }
        __syncthreads();
    }

    const size_t base = ((size_t)(b * H_ + h) * N_);
    float s1p[4], s2p[4];
#pragma unroll
    for (int i = 0; i < 4; i++) {
        int m = m0 + ty * 4 + i;
        size_t di = (base + m) * COUT_ + tx * 4;
        __nv_bfloat16 b0 = __float2bfloat16(acc[i][0]);
        __nv_bfloat16 b1 = __float2bfloat16(acc[i][1]);
        __nv_bfloat16 b2 = __float2bfloat16(acc[i][2]);
        __nv_bfloat16 b3 = __float2bfloat16(acc[i][3]);
        __nv_bfloat162* hp = (__nv_bfloat162*)&g_hbf_hi[di];
        hp[0] = __halves2bfloat162(b0, b1);
        hp[1] = __halves2bfloat162(b2, b3);
        __nv_bfloat162* lp = (__nv_bfloat162*)&g_hbf_lo[di];
        lp[0] = __floats2bfloat162_rn(acc[i][0] - __bfloat162float(b0),
                                      acc[i][1] - __bfloat162float(b1));
        lp[1] = __floats2bfloat162_rn(acc[i][2] - __bfloat162float(b2),
                                      acc[i][3] - __bfloat162float(b3));
        float p1 = acc[i][0] * a1s[tx * 4 + 0] + acc[i][1] * a1s[tx * 4 + 1]
                 + acc[i][2] * a1s[tx * 4 + 2] + acc[i][3] * a1s[tx * 4 + 3];
        float p2 = acc[i][0] * a2s[tx * 4 + 0] + acc[i][1] * a2s[tx * 4 + 1]
                 + acc[i][2] * a2s[tx * 4 + 2] + acc[i][3] * a2s[tx * 4 + 3];
        s1p[i] = p1; s2p[i] = p2;
    }
#pragma unroll
    for (int off = 8; off > 0; off >>= 1) {
#pragma unroll
        for (int i = 0; i < 4; i++) {
            s1p[i] += __shfl_xor_sync(0xffffffffu, s1p[i], off);
            s2p[i] += __shfl_xor_sync(0xffffffffu, s2p[i], off);
        }
    }
    if (tx == 0) {
#pragma unroll
        for (int i = 0; i < 4; i++) {
            sred[ty * 4 + i][0] = s1p[i];
            sred[ty * 4 + i][1] = s2p[i];
        }
    }
    __syncthreads();
    if (t < 64) {
        g_s1[base + m0 + t] = sred[t][0];
        g_s2[base + m0 + t] = sred[t][1];
    }
}

// ---------------------------------------------------------------------------
// Kernel 2: per (b,h): s2max reduce + factor precompute
// ---------------------------------------------------------------------------
__global__ void row_factors() {
    __shared__ float red[256];
    __shared__ float s2max_s;
    int bh = blockIdx.x;
    const float* s1 = g_s1 + bh * N_;
    const float* s2 = g_s2 + bh * N_;
    float m = -1e30f;
    for (int j = threadIdx.x; j < N_; j += 256) m = fmaxf(m, s2[j]);
    red[threadIdx.x] = m;
    __syncthreads();
    for (int s = 128; s > 0; s >>= 1) {
        if (threadIdx.x < s) red[threadIdx.x] = fmaxf(red[threadIdx.x], red[threadIdx.x + s]);
        __syncthreads();
    }
    if (threadIdx.x == 0) s2max_s = red[0];
    __syncthreads();
    const float s2m = s2max_s;
    for (int j = threadIdx.x; j < N_; j += 256) {
        float s1v = s1[j], s2v = s2[j];
        float e = s1v + s2m;
        float M = (e >= 0.f) ? e : ALPHA * e;
        g_A1[bh * N_ + j] = __expf(s1v - M);
        g_A2[bh * N_ + j] = __expf(ALPHA * s1v - M);
        g_B1[bh * N_ + j] = __expf(s2v);
        g_B2[bh * N_ + j] = __expf(ALPHA * s2v);
    }
}

// ---------------------------------------------------------------------------
// Kernel 3: adj -> bitmask, 4 words per loop iteration (MLP 4)
// ---------------------------------------------------------------------------
__global__ void adj_bits_k(const int* __restrict__ adj) {
    int wid  = threadIdx.x >> 5, lane = threadIdx.x & 31;
    int row  = blockIdx.x * 8 + wid;
    const int* ap = adj + (size_t)row * N_;
    unsigned* bp  = g_bits + (size_t)row * (N_ / 32);
#pragma unroll 4
    for (int w2 = 0; w2 < N_ / 128; w2++) {
        int v0 = ap[w2 * 128 + lane];
        int v1 = ap[w2 * 128 + 32 + lane];
        int v2 = ap[w2 * 128 + 64 + lane];
        int v3 = ap[w2 * 128 + 96 + lane];
        unsigned m0 = __ballot_sync(0xffffffffu, v0 > 0);
        unsigned m1 = __ballot_sync(0xffffffffu, v1 > 0);
        unsigned m2 = __ballot_sync(0xffffffffu, v2 > 0);
        unsigned m3 = __ballot_sync(0xffffffffu, v3 > 0);
        if (lane == 0) {
            bp[w2 * 4 + 0] = m0; bp[w2 * 4 + 1] = m1;
            bp[w2 * 4 + 2] = m2; bp[w2 * 4 + 3] = m3;
        }
    }
}

// ---------------------------------------------------------------------------
// Kernel 4 v7: A-fragments computed in registers (no A smem round-trip, no
// weight/MMA barrier); B tiles double-buffered via cp.async; 1 sync per tile.
// CTA = 128 query rows x (b,h); 8 warps; warp w owns rows w*16..+15.
// ---------------------------------------------------------------------------
#define OFF_BB   0          // 2 buffers x (hi 8KB + lo 8KB) = 32 KB
#define OFF_S2F  32768      // float[2048] 8 KB
#define OFF_B1F  40960
#define OFF_B2F  49152
#define OFF_WSUM 57344      // float[128]
#define OFF_BIAS 57856      // float[64]
#define SMEM_TOTAL 58112

__global__ void __launch_bounds__(256) attn_av_mma(const float* __restrict__ bias,
                                                   float* __restrict__ out) {
    extern __shared__ char smem[];
    const uint32_t sb = smem_u32(smem);
    const int b = blockIdx.z, h = blockIdx.y, i0 = blockIdx.x * 128;
    const int bh = b * H_ + h;
    const int t = threadIdx.x, wid = t >> 5, lane = t & 31;

    float* wsum_s = (float*)(smem + OFF_WSUM);
    float* s2f    = (float*)(smem + OFF_S2F);
    float* b1f    = (float*)(smem + OFF_B1F);
    float* b2f    = (float*)(smem + OFF_B2F);
    float* bias_s = (float*)(smem + OFF_BIAS);
    if (t < 16) *(float4*)&bias_s[t * 4] = *(const float4*)&bias[h * COUT_ + t * 4];

    // prologue: stage factor arrays (visible after first loop sync)
    {
        const float* s2g = g_s2 + bh * N_;
        const float* B1g = g_B1 + bh * N_;
        const float* B2g = g_B2 + bh * N_;
#pragma unroll
        for (int r = 0; r < 2; r++) {
            int q = (t + r * 256) * 4;
            *(float4*)&s2f[q] = *(const float4*)&s2g[q];
            *(float4*)&b1f[q] = *(const float4*)&B1g[q];
            *(float4*)&b2f[q] = *(const float4*)&B2g[q];
        }
    }

    // per-lane row identity (mma fragment rows)
    const int m0 = wid * 16;
    const int r0loc = m0 + (lane >> 2);       // row within CTA tile
    const int r1loc = r0loc + 8;
    const float s1_0 = g_s1[bh * N_ + i0 + r0loc];
    const float A1_0 = g_A1[bh * N_ + i0 + r0loc];
    const float A2_0 = g_A2[bh * N_ + i0 + r0loc];
    const float s1_1 = g_s1[bh * N_ + i0 + r1loc];
    const float A1_1 = g_A1[bh * N_ + i0 + r1loc];
    const float A2_1 = g_A2[bh * N_ + i0 + r1loc];
    float lsum0 = 0.f, lsum1 = 0.f;

    const __nv_bfloat16* hHi = g_hbf_hi + (size_t)bh * N_ * COUT_;
    const __nv_bfloat16* hLo = g_hbf_lo + (size_t)bh * N_ * COUT_;
    const unsigned* bpr0 = g_bits + ((size_t)(b * N_ + i0 + r0loc)) * (N_ / 32);
    const unsigned* bpr1 = g_bits + ((size_t)(b * N_ + i0 + r1loc)) * (N_ / 32);

    // ldmatrix B lane addressing (same as proven round-8 layout)
    const int lrow = (lane & 7) + ((lane >> 3) & 1) * 8;
    const int lcol = (lane & 16) ? 16 : 0;
    const int sh_base = (lane & 3) * 2;       // j shift within 32-bit word

    float acc[8][4] = {};

    // stage jt=0 into buffer 0
    {
#pragma unroll
        for (int r = 0; r < 2; r++) {
            int idx = t + r * 256;
            int row = idx >> 3, ch = idx & 7;
            const size_t gsrc = (size_t)row * COUT_ + ch * 8;
            uint32_t so = swz128(row * 128 + ch * 16);
            cp_async16(sb + OFF_BB + so, hHi + gsrc);
            cp_async16(sb + OFF_BB + 8192 + so, hLo + gsrc);
        }
        CP_COMMIT();
    }

    for (int jt = 0; jt < 32; jt++) {
        const int j0 = jt * 64;
        const uint32_t bufb = sb + OFF_BB + (uint32_t)(jt & 1) * 16384;

        CP_WAIT0();
        __syncthreads();      // buf[jt&1] visible; all warps done with jt-1

        // issue cp.async for jt+1 into the other buffer (consumed at jt-1, safe)
        if (jt + 1 < 32) {
            const int j0n = j0 + 64;
            const uint32_t bufn = sb + OFF_BB + (uint32_t)((jt + 1) & 1) * 16384;
#pragma unroll
            for (int r = 0; r < 2; r++) {
                int idx = t + r * 256;
                int row = idx >> 3, ch = idx & 7;
                const size_t gsrc = (size_t)(j0n + row) * COUT_ + ch * 8;
                uint32_t so = swz128(row * 128 + ch * 16);
                cp_async16(bufn + so, hHi + gsrc);
                cp_async16(bufn + 8192 + so, hLo + gsrc);
            }
            CP_COMMIT();
        }

        // adj words for this tile (2 words per row)
        uint2 bitsA = *(const uint2*)&bpr0[jt * 2];
        uint2 bitsB = *(const uint2*)&bpr1[jt * 2];

#pragma unroll
        for (int ks = 0; ks < 4; ks++) {
            const int jb = j0 + sh_base + ks * 16;
            float2 s2a = *(const float2*)&s2f[jb];
            float2 s2b = *(const float2*)&s2f[jb + 8];
            float2 f1a = *(const float2*)&b1f[jb];
            float2 f1b = *(const float2*)&b1f[jb + 8];
            float2 f2a = *(const float2*)&b2f[jb];
            float2 f2b = *(const float2*)&b2f[jb + 8];
            unsigned w0 = (ks < 2) ? bitsA.x : bitsA.y;
            unsigned w1 = (ks < 2) ? bitsB.x : bitsB.y;
            const int sh = sh_base + ((ks & 1) << 4);

            float wa0 = wfun(s1_0, A1_0, A2_0, s2a.x, f1a.x, f2a.x, (w0 >> sh) & 1u);
            float wa1 = wfun(s1_0, A1_0, A2_0, s2a.y, f1a.y, f2a.y, (w0 >> (sh + 1)) & 1u);
            float wa2 = wfun(s1_0, A1_0, A2_0, s2b.x, f1b.x, f2b.x, (w0 >> (sh + 8)) & 1u);
            float wa3 = wfun(s1_0, A1_0, A2_0, s2b.y, f1b.y, f2b.y, (w0 >> (sh + 9)) & 1u);
            float wb0 = wfun(s1_1, A1_1, A2_1, s2a.x, f1a.x, f2a.x, (w1 >> sh) & 1u);
            float wb1 = wfun(s1_1, A1_1, A2_1, s2a.y, f1a.y, f2a.y, (w1 >> (sh + 1)) & 1u);
            float wb2 = wfun(s1_1, A1_1, A2_1, s2b.x, f1b.x, f2b.x, (w1 >> (sh + 8)) & 1u);
            float wb3 = wfun(s1_1, A1_1, A2_1, s2b.y, f1b.y, f2b.y, (w1 >> (sh + 9)) & 1u);
            lsum0 += (wa0 + wa1) + (wa2 + wa3);
            lsum1 += (wb0 + wb1) + (wb2 + wb3);

            uint32_t ah[4], al[4];
            pack_hl(wa0, wa1, ah[0], al[0]);   // row r0, k pair lo
            pack_hl(wb0, wb1, ah[1], al[1]);   // row r1
            pack_hl(wa2, wa3, ah[2], al[2]);   // row r0, k pair +8
            pack_hl(wb2, wb3, ah[3], al[3]);   // row r1

            const uint32_t brow = (uint32_t)(ks * 16 + lrow) * 128 + lcol;
#pragma unroll
            for (int q = 0; q < 4; q++) {
                uint32_t bhf[4], blf[4];
                uint32_t boff = swz128(brow + q * 32);
                ldsm_x4_t(bhf, bufb + boff);
                ldsm_x4_t(blf, bufb + 8192 + boff);
#pragma unroll
                for (int s = 0; s < 2; s++) {
                    int nt = q * 2 + s;
                    mma_bf16(acc[nt], ah, &bhf[s * 2]);
                    mma_bf16(acc[nt], ah, &blf[s * 2]);
                    mma_bf16(acc[nt], al, &bhf[s * 2]);
                }
            }
        }
    }

    // row-sum reduce across the 4 lanes sharing each fragment row
    lsum0 += __shfl_xor_sync(0xffffffffu, lsum0, 1);
    lsum0 += __shfl_xor_sync(0xffffffffu, lsum0, 2);
    lsum1 += __shfl_xor_sync(0xffffffffu, lsum1, 1);
    lsum1 += __shfl_xor_sync(0xffffffffu, lsum1, 2);
    if ((lane & 3) == 0) {
        wsum_s[r0loc] = lsum0;
        wsum_s[r1loc] = lsum1;
    }
    __syncthreads();

    // ---- epilogue ----
    const float inv0 = 1.f / wsum_s[r0loc];
    const float inv1 = 1.f / wsum_s[r1loc];
    float* op0 = out + ((size_t)(b * N_ + i0 + r0loc)) * (H_ * COUT_) + h * COUT_;
    float* op1 = out + ((size_t)(b * N_ + i0 + r1loc)) * (H_ * COUT_) + h * COUT_;
#pragma unroll
    for (int nt = 0; nt < 8; nt++) {
        int col = nt * 8 + (lane & 3) * 2;
        float bx = bias_s[col], by = bias_s[col + 1];
        float2 o0, o1;
        o0.x = fmaxf(acc[nt][0] * inv0 + bx, 0.f);
        o0.y = fmaxf(acc[nt][1] * inv0 + by, 0.f);
        o1.x = fmaxf(acc[nt][2] * inv1 + bx, 0.f);
        o1.y = fmaxf(acc[nt][3] * inv1 + by, 0.f);
        *(float2*)&op0[col] = o0;
        *(float2*)&op1[col] = o1;
    }
}

// ---------------------------------------------------------------------------
extern "C" void kernel_launch(void* const* d_in, const int* in_sizes, int n_in,
                              void* d_out, int out_size) {
    const float* x    = (const float*)d_in[0];
    const int*   adj  = (const int*)  d_in[1];
    const float* W    = (const float*)d_in[2];
    const float* a    = (const float*)d_in[3];
    const float* bias = (const float*)d_in[4];
    float* out = (float*)d_out;

    cudaFuncSetAttribute(attn_av_mma, cudaFuncAttributeMaxDynamicSharedMemorySize,
                         SMEM_TOTAL);

    adj_bits_k<<<(B_ * N_) / 8, 256>>>(adj);

    dim3 g1(N_ / 64, H_, B_);
    gemm_hidden<<<g1, 256>>>(x, W, a);

    row_factors<<<B_ * H_, 256>>>();

    dim3 g4(N_ / 128, H_, B_);
    attn_av_mma<<<g4, 256, SMEM_TOTAL>>>(bias, out);
}

// round 11
// speedup vs baseline: 1.5909x; 1.0375x over previous
#include <cuda_runtime.h>
#include <cuda_bf16.h>
#include <cstdint>

#define B_    4
#define N_    2048
#define CIN_  256
#define COUT_ 64
#define H_    8
#define ALPHA 0.2f

// ---------------- scratch (__device__ globals; no allocs allowed) -----------
__device__ __nv_bfloat16 g_hbf_hi[(size_t)B_ * H_ * N_ * COUT_];  // [bh][n][c]
__device__ __nv_bfloat16 g_hbf_lo[(size_t)B_ * H_ * N_ * COUT_];
__device__ float g_s1[B_ * H_ * N_];
__device__ float g_s2[B_ * H_ * N_];
__device__ float g_A1[B_ * H_ * N_];    // exp(s1 - M)
__device__ float g_A2[B_ * H_ * N_];    // exp(0.2 s1 - M)
__device__ float g_B1[B_ * H_ * N_];    // exp(s2)
__device__ float g_B2[B_ * H_ * N_];    // exp(0.2 s2)
__device__ unsigned g_bits[(size_t)B_ * N_ * (N_ / 32)];          // adj bitmask

// ---------------- helpers (sm_80-era PTX only) ------------------------------
__device__ __forceinline__ uint32_t smem_u32(const void* p) {
    uint32_t a;
    asm("{ .reg .u64 t; cvta.to.shared.u64 t, %1; cvt.u32.u64 %0, t; }"
        : "=r"(a) : "l"(p));
    return a;
}
__device__ __forceinline__ uint32_t swz128(uint32_t off) {
    return off ^ ((off >> 3) & 0x70);
}
__device__ __forceinline__ void ldsm_x4_t(uint32_t* r, uint32_t addr) {
    asm volatile("ldmatrix.sync.aligned.m8n8.x4.trans.shared.b16 {%0,%1,%2,%3}, [%4];"
                 : "=r"(r[0]), "=r"(r[1]), "=r"(r[2]), "=r"(r[3]) : "r"(addr));
}
__device__ __forceinline__ void mma_bf16(float* c, const uint32_t* a, const uint32_t* b) {
    asm volatile("mma.sync.aligned.m16n8k16.row.col.f32.bf16.bf16.f32 "
                 "{%0,%1,%2,%3}, {%4,%5,%6,%7}, {%8,%9}, {%0,%1,%2,%3};"
                 : "+f"(c[0]), "+f"(c[1]), "+f"(c[2]), "+f"(c[3])
                 : "r"(a[0]), "r"(a[1]), "r"(a[2]), "r"(a[3]), "r"(b[0]), "r"(b[1]));
}
__device__ __forceinline__ void cp_async16(uint32_t dst, const void* src) {
    asm volatile("cp.async.cg.shared.global [%0], [%1], 16;"
                 :: "r"(dst), "l"(src) : "memory");
}
#define CP_COMMIT() asm volatile("cp.async.commit_group;" ::: "memory")
#define CP_WAIT0()  asm volatile("cp.async.wait_group 0;" ::: "memory")

// weight: exp(leaky(s1+s2)-M) = max(A1*B1, A2*B2)  (leaky(e)=max(e,0.2e), exp monotone)
__device__ __forceinline__ float wfun(float A1, float A2,
                                      float f1, float f2, unsigned bit) {
    float w = fmaxf(A1 * f1, A2 * f2);
    return bit ? w : 0.f;
}
// truncation hi/lo split of two weights -> packed bf16x2 hi + bf16x2 lo
__device__ __forceinline__ void pack_hl(float x, float y, uint32_t& hi, uint32_t& lo) {
    uint32_t u0 = __float_as_uint(x), u1 = __float_as_uint(y);
    uint32_t h0 = u0 & 0xFFFF0000u, h1 = u1 & 0xFFFF0000u;
    hi = __byte_perm(h0, h1, 0x7632);                 // {bf16(y), bf16(x)}
    float l0 = x - __uint_as_float(h0);
    float l1 = y - __uint_as_float(h1);
    __nv_bfloat162 lq = __floats2bfloat162_rn(l0, l1);
    lo = *(uint32_t*)&lq;
}

// ---------------------------------------------------------------------------
// Kernel 1: hidden = x @ W^T ; epilogue emits bf16 hi/lo AND fused s1/s2 scores
// ---------------------------------------------------------------------------
__global__ void gemm_hidden(const float* __restrict__ x,
                            const float* __restrict__ Wf,
                            const float* __restrict__ av) {
    const int b  = blockIdx.z;
    const int m0 = blockIdx.x * 64;
    const int h  = blockIdx.y;
    const int col0 = h * 64;
    __shared__ float As[32][68];
    __shared__ float Bs[32][68];
    __shared__ float a1s[64], a2s[64];
    __shared__ float sred[64][2];
    const int t  = threadIdx.x;
    const int tx = t & 15, ty = t >> 4;
    float acc[4][4] = {};
    const float* xb = x + (size_t)b * N_ * CIN_;

    if (t < 64) { a1s[t] = av[h * 128 + t]; a2s[t] = av[h * 128 + 64 + t]; }

    for (int k0 = 0; k0 < CIN_; k0 += 32) {
#pragma unroll
        for (int r = 0; r < 2; r++) {
            int fidx = t + r * 256;
            int row  = fidx >> 3;
            int c4   = (fidx & 7) * 4;
            float4 v = *(const float4*)&xb[(size_t)(m0 + row) * CIN_ + k0 + c4];
            As[c4 + 0][row] = v.x; As[c4 + 1][row] = v.y;
            As[c4 + 2][row] = v.z; As[c4 + 3][row] = v.w;
            float4 w = *(const float4*)&Wf[(size_t)(col0 + row) * CIN_ + k0 + c4];
            Bs[c4 + 0][row] = w.x; Bs[c4 + 1][row] = w.y;
            Bs[c4 + 2][row] = w.z; Bs[c4 + 3][row] = w.w;
        }
        __syncthreads();
#pragma unroll
        for (int kk = 0; kk < 32; kk++) {
            float4 rm = *(const float4*)&As[kk][ty * 4];
            float4 rn = *(const float4*)&Bs[kk][tx * 4];
            float am[4] = {rm.x, rm.y, rm.z, rm.w};
            float an[4] = {rn.x, rn.y, rn.z, rn.w};
#pragma unroll
            for (int i = 0; i < 4; i++)
#pragma unroll
                for (int j = 0; j < 4; j++)
                    acc[i][j] += am[i] * an[j];
        }
        __syncthreads();
    }

    const size_t base = ((size_t)(b * H_ + h) * N_);
    float s1p[4], s2p[4];
#pragma unroll
    for (int i = 0; i < 4; i++) {
        int m = m0 + ty * 4 + i;
        size_t di = (base + m) * COUT_ + tx * 4;
        __nv_bfloat16 b0 = __float2bfloat16(acc[i][0]);
        __nv_bfloat16 b1 = __float2bfloat16(acc[i][1]);
        __nv_bfloat16 b2 = __float2bfloat16(acc[i][2]);
        __nv_bfloat16 b3 = __float2bfloat16(acc[i][3]);
        __nv_bfloat162* hp = (__nv_bfloat162*)&g_hbf_hi[di];
        hp[0] = __halves2bfloat162(b0, b1);
        hp[1] = __halves2bfloat162(b2, b3);
        __nv_bfloat162* lp = (__nv_bfloat162*)&g_hbf_lo[di];
        lp[0] = __floats2bfloat162_rn(acc[i][0] - __bfloat162float(b0),
                                      acc[i][1] - __bfloat162float(b1));
        lp[1] = __floats2bfloat162_rn(acc[i][2] - __bfloat162float(b2),
                                      acc[i][3] - __bfloat162float(b3));
        float p1 = acc[i][0] * a1s[tx * 4 + 0] + acc[i][1] * a1s[tx * 4 + 1]
                 + acc[i][2] * a1s[tx * 4 + 2] + acc[i][3] * a1s[tx * 4 + 3];
        float p2 = acc[i][0] * a2s[tx * 4 + 0] + acc[i][1] * a2s[tx * 4 + 1]
                 + acc[i][2] * a2s[tx * 4 + 2] + acc[i][3] * a2s[tx * 4 + 3];
        s1p[i] = p1; s2p[i] = p2;
    }
#pragma unroll
    for (int off = 8; off > 0; off >>= 1) {
#pragma unroll
        for (int i = 0; i < 4; i++) {
            s1p[i] += __shfl_xor_sync(0xffffffffu, s1p[i], off);
            s2p[i] += __shfl_xor_sync(0xffffffffu, s2p[i], off);
        }
    }
    if (tx == 0) {
#pragma unroll
        for (int i = 0; i < 4; i++) {
            sred[ty * 4 + i][0] = s1p[i];
            sred[ty * 4 + i][1] = s2p[i];
        }
    }
    __syncthreads();
    if (t < 64) {
        g_s1[base + m0 + t] = sred[t][0];
        g_s2[base + m0 + t] = sred[t][1];
    }
}

// ---------------------------------------------------------------------------
// Kernel 2: per (b,h): s2max reduce + factor precompute
// ---------------------------------------------------------------------------
__global__ void row_factors() {
    __shared__ float red[256];
    __shared__ float s2max_s;
    int bh = blockIdx.x;
    const float* s1 = g_s1 + bh * N_;
    const float* s2 = g_s2 + bh * N_;
    float m = -1e30f;
    for (int j = threadIdx.x; j < N_; j += 256) m = fmaxf(m, s2[j]);
    red[threadIdx.x] = m;
    __syncthreads();
    for (int s = 128; s > 0; s >>= 1) {
        if (threadIdx.x < s) red[threadIdx.x] = fmaxf(red[threadIdx.x], red[threadIdx.x + s]);
        __syncthreads();
    }
    if (threadIdx.x == 0) s2max_s = red[0];
    __syncthreads();
    const float s2m = s2max_s;
    for (int j = threadIdx.x; j < N_; j += 256) {
        float s1v = s1[j], s2v = s2[j];
        float e = s1v + s2m;
        float M = (e >= 0.f) ? e : ALPHA * e;
        g_A1[bh * N_ + j] = __expf(s1v - M);
        g_A2[bh * N_ + j] = __expf(ALPHA * s1v - M);
        g_B1[bh * N_ + j] = __expf(s2v);
        g_B2[bh * N_ + j] = __expf(ALPHA * s2v);
    }
}

// ---------------------------------------------------------------------------
// Kernel 3: adj -> bitmask, 4 words per loop iteration (MLP 4)
// ---------------------------------------------------------------------------
__global__ void adj_bits_k(const int* __restrict__ adj) {
    int wid  = threadIdx.x >> 5, lane = threadIdx.x & 31;
    int row  = blockIdx.x * 8 + wid;
    const int* ap = adj + (size_t)row * N_;
    unsigned* bp  = g_bits + (size_t)row * (N_ / 32);
#pragma unroll 4
    for (int w2 = 0; w2 < N_ / 128; w2++) {
        int v0 = ap[w2 * 128 + lane];
        int v1 = ap[w2 * 128 + 32 + lane];
        int v2 = ap[w2 * 128 + 64 + lane];
        int v3 = ap[w2 * 128 + 96 + lane];
        unsigned m0 = __ballot_sync(0xffffffffu, v0 > 0);
        unsigned m1 = __ballot_sync(0xffffffffu, v1 > 0);
        unsigned m2 = __ballot_sync(0xffffffffu, v2 > 0);
        unsigned m3 = __ballot_sync(0xffffffffu, v3 > 0);
        if (lane == 0) {
            bp[w2 * 4 + 0] = m0; bp[w2 * 4 + 1] = m1;
            bp[w2 * 4 + 2] = m2; bp[w2 * 4 + 3] = m3;
        }
    }
}

// ---------------------------------------------------------------------------
// Kernel 4 v8: max-trick weight eval (w = max(A1*B1, A2*B2); no s2/predicate),
// register A-fragments, double-buffered cp.async B, 1 sync per tile.
// ---------------------------------------------------------------------------
#define OFF_BB   0          // 2 buffers x (hi 8KB + lo 8KB) = 32 KB
#define OFF_B1F  32768      // float[2048] 8 KB
#define OFF_B2F  40960      // float[2048] 8 KB
#define OFF_WSUM 49152      // float[128]
#define OFF_BIAS 49664      // float[64]
#define SMEM_TOTAL 49920

__global__ void __launch_bounds__(256) attn_av_mma(const float* __restrict__ bias,
                                                   float* __restrict__ out) {
    extern __shared__ char smem[];
    const uint32_t sb = smem_u32(smem);
    const int b = blockIdx.z, h = blockIdx.y, i0 = blockIdx.x * 128;
    const int bh = b * H_ + h;
    const int t = threadIdx.x, wid = t >> 5, lane = t & 31;

    float* wsum_s = (float*)(smem + OFF_WSUM);
    float* b1f    = (float*)(smem + OFF_B1F);
    float* b2f    = (float*)(smem + OFF_B2F);
    float* bias_s = (float*)(smem + OFF_BIAS);
    if (t < 16) *(float4*)&bias_s[t * 4] = *(const float4*)&bias[h * COUT_ + t * 4];

    // prologue: stage factor arrays (visible after first loop sync)
    {
        const float* B1g = g_B1 + bh * N_;
        const float* B2g = g_B2 + bh * N_;
#pragma unroll
        for (int r = 0; r < 2; r++) {
            int q = (t + r * 256) * 4;
            *(float4*)&b1f[q] = *(const float4*)&B1g[q];
            *(float4*)&b2f[q] = *(const float4*)&B2g[q];
        }
    }

    // per-lane row identity (mma fragment rows)
    const int m0 = wid * 16;
    const int r0loc = m0 + (lane >> 2);
    const int r1loc = r0loc + 8;
    const float A1_0 = g_A1[bh * N_ + i0 + r0loc];
    const float A2_0 = g_A2[bh * N_ + i0 + r0loc];
    const float A1_1 = g_A1[bh * N_ + i0 + r1loc];
    const float A2_1 = g_A2[bh * N_ + i0 + r1loc];
    float lsum0 = 0.f, lsum1 = 0.f;

    const __nv_bfloat16* hHi = g_hbf_hi + (size_t)bh * N_ * COUT_;
    const __nv_bfloat16* hLo = g_hbf_lo + (size_t)bh * N_ * COUT_;
    const unsigned* bpr0 = g_bits + ((size_t)(b * N_ + i0 + r0loc)) * (N_ / 32);
    const unsigned* bpr1 = g_bits + ((size_t)(b * N_ + i0 + r1loc)) * (N_ / 32);

    const int lrow = (lane & 7) + ((lane >> 3) & 1) * 8;
    const int lcol = (lane & 16) ? 16 : 0;
    const int sh_base = (lane & 3) * 2;

    float acc[8][4] = {};

    // stage jt=0 into buffer 0
    {
#pragma unroll
        for (int r = 0; r < 2; r++) {
            int idx = t + r * 256;
            int row = idx >> 3, ch = idx & 7;
            const size_t gsrc = (size_t)row * COUT_ + ch * 8;
            uint32_t so = swz128(row * 128 + ch * 16);
            cp_async16(sb + OFF_BB + so, hHi + gsrc);
            cp_async16(sb + OFF_BB + 8192 + so, hLo + gsrc);
        }
        CP_COMMIT();
    }

    for (int jt = 0; jt < 32; jt++) {
        const int j0 = jt * 64;
        const uint32_t bufb = sb + OFF_BB + (uint32_t)(jt & 1) * 16384;

        CP_WAIT0();
        __syncthreads();      // buf[jt&1] visible; all warps done with jt-1

        // cp.async for jt+1 into the other buffer
        if (jt + 1 < 32) {
            const int j0n = j0 + 64;
            const uint32_t bufn = sb + OFF_BB + (uint32_t)((jt + 1) & 1) * 16384;
#pragma unroll
            for (int r = 0; r < 2; r++) {
                int idx = t + r * 256;
                int row = idx >> 3, ch = idx & 7;
                const size_t gsrc = (size_t)(j0n + row) * COUT_ + ch * 8;
                uint32_t so = swz128(row * 128 + ch * 16);
                cp_async16(bufn + so, hHi + gsrc);
                cp_async16(bufn + 8192 + so, hLo + gsrc);
            }
            CP_COMMIT();
        }

        uint2 bitsA = *(const uint2*)&bpr0[jt * 2];
        uint2 bitsB = *(const uint2*)&bpr1[jt * 2];

#pragma unroll
        for (int ks = 0; ks < 4; ks++) {
            const int jb = j0 + sh_base + ks * 16;
            float2 f1a = *(const float2*)&b1f[jb];
            float2 f1b = *(const float2*)&b1f[jb + 8];
            float2 f2a = *(const float2*)&b2f[jb];
            float2 f2b = *(const float2*)&b2f[jb + 8];
            unsigned w0 = (ks < 2) ? bitsA.x : bitsA.y;
            unsigned w1 = (ks < 2) ? bitsB.x : bitsB.y;
            const int sh = sh_base + ((ks & 1) << 4);

            float wa0 = wfun(A1_0, A2_0, f1a.x, f2a.x, (w0 >> sh) & 1u);
            float wa1 = wfun(A1_0, A2_0, f1a.y, f2a.y, (w0 >> (sh + 1)) & 1u);
            float wa2 = wfun(A1_0, A2_0, f1b.x, f2b.x, (w0 >> (sh + 8)) & 1u);
            float wa3 = wfun(A1_0, A2_0, f1b.y, f2b.y, (w0 >> (sh + 9)) & 1u);
            float wb0 = wfun(A1_1, A2_1, f1a.x, f2a.x, (w1 >> sh) & 1u);
            float wb1 = wfun(A1_1, A2_1, f1a.y, f2a.y, (w1 >> (sh + 1)) & 1u);
            float wb2 = wfun(A1_1, A2_1, f1b.x, f2b.x, (w1 >> (sh + 8)) & 1u);
            float wb3 = wfun(A1_1, A2_1, f1b.y, f2b.y, (w1 >> (sh + 9)) & 1u);
            lsum0 += (wa0 + wa1) + (wa2 + wa3);
            lsum1 += (wb0 + wb1) + (wb2 + wb3);

            uint32_t ah[4], al[4];
            pack_hl(wa0, wa1, ah[0], al[0]);
            pack_hl(wb0, wb1, ah[1], al[1]);
            pack_hl(wa2, wa3, ah[2], al[2]);
            pack_hl(wb2, wb3, ah[3], al[3]);

            const uint32_t brow = (uint32_t)(ks * 16 + lrow) * 128 + lcol;
#pragma unroll
            for (int q = 0; q < 4; q++) {
                uint32_t bhf[4], blf[4];
                uint32_t boff = swz128(brow + q * 32);
                ldsm_x4_t(bhf, bufb + boff);
                ldsm_x4_t(blf, bufb + 8192 + boff);
#pragma unroll
                for (int s = 0; s < 2; s++) {
                    int nt = q * 2 + s;
                    mma_bf16(acc[nt], ah, &bhf[s * 2]);
                    mma_bf16(acc[nt], ah, &blf[s * 2]);
                    mma_bf16(acc[nt], al, &bhf[s * 2]);
                }
            }
        }
    }

    // row-sum reduce across the 4 lanes sharing each fragment row
    lsum0 += __shfl_xor_sync(0xffffffffu, lsum0, 1);
    lsum0 += __shfl_xor_sync(0xffffffffu, lsum0, 2);
    lsum1 += __shfl_xor_sync(0xffffffffu, lsum1, 1);
    lsum1 += __shfl_xor_sync(0xffffffffu, lsum1, 2);
    if ((lane & 3) == 0) {
        wsum_s[r0loc] = lsum0;
        wsum_s[r1loc] = lsum1;
    }
    __syncthreads();

    // ---- epilogue ----
    const float inv0 = 1.f / wsum_s[r0loc];
    const float inv1 = 1.f / wsum_s[r1loc];
    float* op0 = out + ((size_t)(b * N_ + i0 + r0loc)) * (H_ * COUT_) + h * COUT_;
    float* op1 = out + ((size_t)(b * N_ + i0 + r1loc)) * (H_ * COUT_) + h * COUT_;
#pragma unroll
    for (int nt = 0; nt < 8; nt++) {
        int col = nt * 8 + (lane & 3) * 2;
        float bx = bias_s[col], by = bias_s[col + 1];
        float2 o0, o1;
        o0.x = fmaxf(acc[nt][0] * inv0 + bx, 0.f);
        o0.y = fmaxf(acc[nt][1] * inv0 + by, 0.f);
        o1.x = fmaxf(acc[nt][2] * inv1 + bx, 0.f);
        o1.y = fmaxf(acc[nt][3] * inv1 + by, 0.f);
        *(float2*)&op0[col] = o0;
        *(float2*)&op1[col] = o1;
    }
}

// ---------------------------------------------------------------------------
extern "C" void kernel_launch(void* const* d_in, const int* in_sizes, int n_in,
                              void* d_out, int out_size) {
    const float* x    = (const float*)d_in[0];
    const int*   adj  = (const int*)  d_in[1];
    const float* W    = (const float*)d_in[2];
    const float* a    = (const float*)d_in[3];
    const float* bias = (const float*)d_in[4];
    float* out = (float*)d_out;

    cudaFuncSetAttribute(attn_av_mma, cudaFuncAttributeMaxDynamicSharedMemorySize,
                         SMEM_TOTAL);

    adj_bits_k<<<(B_ * N_) / 8, 256>>>(adj);

    dim3 g1(N_ / 64, H_, B_);
    gemm_hidden<<<g1, 256>>>(x, W, a);

    row_factors<<<B_ * H_, 256>>>();

    dim3 g4(N_ / 128, H_, B_);
    attn_av_mma<<<g4, 256, SMEM_TOTAL>>>(bias, out);
}

// round 12
// speedup vs baseline: 1.7131x; 1.0768x over previous
#include <cuda_runtime.h>
#include <cuda_bf16.h>
#include <cstdint>

#define B_    4
#define N_    2048
#define CIN_  256
#define COUT_ 64
#define H_    8
#define ALPHA 0.2f

// ---------------- scratch (__device__ globals; no allocs allowed) -----------
__device__ float g_htf[(size_t)B_ * H_ * N_ * COUT_];   // hidden, tf32-rounded f32
__device__ float g_s1[B_ * H_ * N_];
__device__ float g_s2[B_ * H_ * N_];
__device__ float g_A1[B_ * H_ * N_];    // exp(s1 - M)
__device__ float g_A2[B_ * H_ * N_];    // exp(0.2 s1 - M)
__device__ float g_B1[B_ * H_ * N_];    // exp(s2)
__device__ float g_B2[B_ * H_ * N_];    // exp(0.2 s2)
__device__ unsigned g_bits[(size_t)B_ * N_ * (N_ / 32)];          // adj bitmask

// ---------------- helpers (sm_80-era PTX only) ------------------------------
__device__ __forceinline__ uint32_t smem_u32(const void* p) {
    uint32_t a;
    asm("{ .reg .u64 t; cvta.to.shared.u64 t, %1; cvt.u32.u64 %0, t; }"
        : "=r"(a) : "l"(p));
    return a;
}
__device__ __forceinline__ uint32_t to_tf32(float x) {
    uint32_t r;
    asm("cvt.rna.tf32.f32 %0, %1;" : "=r"(r) : "f"(x));
    return r;
}
__device__ __forceinline__ void mma_tf32(float* c, const uint32_t* a,
                                         uint32_t b0, uint32_t b1) {
    asm volatile("mma.sync.aligned.m16n8k8.row.col.f32.tf32.tf32.f32 "
                 "{%0,%1,%2,%3}, {%4,%5,%6,%7}, {%8,%9}, {%0,%1,%2,%3};"
                 : "+f"(c[0]), "+f"(c[1]), "+f"(c[2]), "+f"(c[3])
                 : "r"(a[0]), "r"(a[1]), "r"(a[2]), "r"(a[3]), "r"(b0), "r"(b1));
}
__device__ __forceinline__ void cp_async16(uint32_t dst, const void* src) {
    asm volatile("cp.async.cg.shared.global [%0], [%1], 16;"
                 :: "r"(dst), "l"(src) : "memory");
}
#define CP_COMMIT() asm volatile("cp.async.commit_group;" ::: "memory")
#define CP_WAIT0()  asm volatile("cp.async.wait_group 0;" ::: "memory")

// weight: exp(leaky(s1+s2)-M) = max(A1*B1, A2*B2)
__device__ __forceinline__ float wfun(float A1, float A2,
                                      float f1, float f2, unsigned bit) {
    float w = fmaxf(A1 * f1, A2 * f2);
    return bit ? w : 0.f;
}

// ---------------------------------------------------------------------------
// Kernel 1: hidden = x @ W^T ; epilogue emits tf32-rounded f32 + fused scores
// ---------------------------------------------------------------------------
__global__ void gemm_hidden(const float* __restrict__ x,
                            const float* __restrict__ Wf,
                            const float* __restrict__ av) {
    const int b  = blockIdx.z;
    const int m0 = blockIdx.x * 64;
    const int h  = blockIdx.y;
    const int col0 = h * 64;
    __shared__ float As[32][68];
    __shared__ float Bs[32][68];
    __shared__ float a1s[64], a2s[64];
    __shared__ float sred[64][2];
    const int t  = threadIdx.x;
    const int tx = t & 15, ty = t >> 4;
    float acc[4][4] = {};
    const float* xb = x + (size_t)b * N_ * CIN_;

    if (t < 64) { a1s[t] = av[h * 128 + t]; a2s[t] = av[h * 128 + 64 + t]; }

    for (int k0 = 0; k0 < CIN_; k0 += 32) {
#pragma unroll
        for (int r = 0; r < 2; r++) {
            int fidx = t + r * 256;
            int row  = fidx >> 3;
            int c4   = (fidx & 7) * 4;
            float4 v = *(const float4*)&xb[(size_t)(m0 + row) * CIN_ + k0 + c4];
            As[c4 + 0][row] = v.x; As[c4 + 1][row] = v.y;
            As[c4 + 2][row] = v.z; As[c4 + 3][row] = v.w;
            float4 w = *(const float4*)&Wf[(size_t)(col0 + row) * CIN_ + k0 + c4];
            Bs[c4 + 0][row] = w.x; Bs[c4 + 1][row] = w.y;
            Bs[c4 + 2][row] = w.z; Bs[c4 + 3][row] = w.w;
        }
        __syncthreads();
#pragma unroll
        for (int kk = 0; kk < 32; kk++) {
            float4 rm = *(const float4*)&As[kk][ty * 4];
            float4 rn = *(const float4*)&Bs[kk][tx * 4];
            float am[4] = {rm.x, rm.y, rm.z, rm.w};
            float an[4] = {rn.x, rn.y, rn.z, rn.w};
#pragma unroll
            for (int i = 0; i < 4; i++)
#pragma unroll
                for (int j = 0; j < 4; j++)
                    acc[i][j] += am[i] * an[j];
        }
        __syncthreads();
    }

    const size_t base = ((size_t)(b * H_ + h) * N_);
    float s1p[4], s2p[4];
#pragma unroll
    for (int i = 0; i < 4; i++) {
        int m = m0 + ty * 4 + i;
        size_t di = (base + m) * COUT_ + tx * 4;
        float4 o;
        o.x = __uint_as_float(to_tf32(acc[i][0]));
        o.y = __uint_as_float(to_tf32(acc[i][1]));
        o.z = __uint_as_float(to_tf32(acc[i][2]));
        o.w = __uint_as_float(to_tf32(acc[i][3]));
        *(float4*)&g_htf[di] = o;
        float p1 = acc[i][0] * a1s[tx * 4 + 0] + acc[i][1] * a1s[tx * 4 + 1]
                 + acc[i][2] * a1s[tx * 4 + 2] + acc[i][3] * a1s[tx * 4 + 3];
        float p2 = acc[i][0] * a2s[tx * 4 + 0] + acc[i][1] * a2s[tx * 4 + 1]
                 + acc[i][2] * a2s[tx * 4 + 2] + acc[i][3] * a2s[tx * 4 + 3];
        s1p[i] = p1; s2p[i] = p2;
    }
#pragma unroll
    for (int off = 8; off > 0; off >>= 1) {
#pragma unroll
        for (int i = 0; i < 4; i++) {
            s1p[i] += __shfl_xor_sync(0xffffffffu, s1p[i], off);
            s2p[i] += __shfl_xor_sync(0xffffffffu, s2p[i], off);
        }
    }
    if (tx == 0) {
#pragma unroll
        for (int i = 0; i < 4; i++) {
            sred[ty * 4 + i][0] = s1p[i];
            sred[ty * 4 + i][1] = s2p[i];
        }
    }
    __syncthreads();
    if (t < 64) {
        g_s1[base + m0 + t] = sred[t][0];
        g_s2[base + m0 + t] = sred[t][1];
    }
}

// ---------------------------------------------------------------------------
// Kernel 2: per (b,h): s2max reduce + factor precompute
// ---------------------------------------------------------------------------
__global__ void row_factors() {
    __shared__ float red[256];
    __shared__ float s2max_s;
    int bh = blockIdx.x;
    const float* s1 = g_s1 + bh * N_;
    const float* s2 = g_s2 + bh * N_;
    float m = -1e30f;
    for (int j = threadIdx.x; j < N_; j += 256) m = fmaxf(m, s2[j]);
    red[threadIdx.x] = m;
    __syncthreads();
    for (int s = 128; s > 0; s >>= 1) {
        if (threadIdx.x < s) red[threadIdx.x] = fmaxf(red[threadIdx.x], red[threadIdx.x + s]);
        __syncthreads();
    }
    if (threadIdx.x == 0) s2max_s = red[0];
    __syncthreads();
    const float s2m = s2max_s;
    for (int j = threadIdx.x; j < N_; j += 256) {
        float s1v = s1[j], s2v = s2[j];
        float e = s1v + s2m;
        float M = (e >= 0.f) ? e : ALPHA * e;
        g_A1[bh * N_ + j] = __expf(s1v - M);
        g_A2[bh * N_ + j] = __expf(ALPHA * s1v - M);
        g_B1[bh * N_ + j] = __expf(s2v);
        g_B2[bh * N_ + j] = __expf(ALPHA * s2v);
    }
}

// ---------------------------------------------------------------------------
// Kernel 3: adj -> bitmask, 4 words per loop iteration (MLP 4)
// ---------------------------------------------------------------------------
__global__ void adj_bits_k(const int* __restrict__ adj) {
    int wid  = threadIdx.x >> 5, lane = threadIdx.x & 31;
    int row  = blockIdx.x * 8 + wid;
    const int* ap = adj + (size_t)row * N_;
    unsigned* bp  = g_bits + (size_t)row * (N_ / 32);
#pragma unroll 4
    for (int w2 = 0; w2 < N_ / 128; w2++) {
        int v0 = ap[w2 * 128 + lane];
        int v1 = ap[w2 * 128 + 32 + lane];
        int v2 = ap[w2 * 128 + 64 + lane];
        int v3 = ap[w2 * 128 + 96 + lane];
        unsigned m0 = __ballot_sync(0xffffffffu, v0 > 0);
        unsigned m1 = __ballot_sync(0xffffffffu, v1 > 0);
        unsigned m2 = __ballot_sync(0xffffffffu, v2 > 0);
        unsigned m3 = __ballot_sync(0xffffffffu, v3 > 0);
        if (lane == 0) {
            bp[w2 * 4 + 0] = m0; bp[w2 * 4 + 1] = m1;
            bp[w2 * 4 + 2] = m2; bp[w2 * 4 + 3] = m3;
        }
    }
}

// ---------------------------------------------------------------------------
// Kernel 4 v9: single-term tf32 MMA (m16n8k8). A-fragments built in registers
// (4 cvt.rna per k8), B tiles f32 double-buffered (pitch 72: conflict-free),
// 1 sync per tile. CTA = 128 query rows x (b,h); 8 warps.
// ---------------------------------------------------------------------------
#define BPITCH   72                           // floats per B row (bank-spread)
#define BUF_FL   (64 * BPITCH)                // 4608 floats = 18432 B
#define OFF_BB   0                            // 2 x 18432 = 36864
#define OFF_B1F  36864                        // float[2048] 8 KB
#define OFF_B2F  45056                        // float[2048] 8 KB
#define OFF_WSUM 53248                        // float[128]
#define OFF_BIAS 53760                        // float[64]
#define SMEM_TOTAL 54016

__global__ void __launch_bounds__(256) attn_av_mma(const float* __restrict__ bias,
                                                   float* __restrict__ out) {
    extern __shared__ char smem[];
    const uint32_t sb = smem_u32(smem);
    const int b = blockIdx.z, h = blockIdx.y, i0 = blockIdx.x * 128;
    const int bh = b * H_ + h;
    const int t = threadIdx.x, wid = t >> 5, lane = t & 31;

    float* wsum_s = (float*)(smem + OFF_WSUM);
    float* b1f    = (float*)(smem + OFF_B1F);
    float* b2f    = (float*)(smem + OFF_B2F);
    float* bias_s = (float*)(smem + OFF_BIAS);
    float* Bbuf   = (float*)(smem + OFF_BB);
    if (t < 16) *(float4*)&bias_s[t * 4] = *(const float4*)&bias[h * COUT_ + t * 4];

    // prologue: stage factor arrays (visible after first loop sync)
    {
        const float* B1g = g_B1 + bh * N_;
        const float* B2g = g_B2 + bh * N_;
#pragma unroll
        for (int r = 0; r < 2; r++) {
            int q = (t + r * 256) * 4;
            *(float4*)&b1f[q] = *(const float4*)&B1g[q];
            *(float4*)&b2f[q] = *(const float4*)&B2g[q];
        }
    }

    // per-lane row identity (mma fragment rows)
    const int m0 = wid * 16;
    const int r0loc = m0 + (lane >> 2);
    const int r1loc = r0loc + 8;
    const int la = lane & 3;                 // k-in-group
    const int gn = lane >> 2;                // n-in-group
    const float A1_0 = g_A1[bh * N_ + i0 + r0loc];
    const float A2_0 = g_A2[bh * N_ + i0 + r0loc];
    const float A1_1 = g_A1[bh * N_ + i0 + r1loc];
    const float A2_1 = g_A2[bh * N_ + i0 + r1loc];
    float lsum0 = 0.f, lsum1 = 0.f;

    const float* hT = g_htf + (size_t)bh * N_ * COUT_;
    const unsigned* bpr0 = g_bits + ((size_t)(b * N_ + i0 + r0loc)) * (N_ / 32);
    const unsigned* bpr1 = g_bits + ((size_t)(b * N_ + i0 + r1loc)) * (N_ / 32);

    float acc[8][4] = {};

    // stage jt=0 into buffer 0 (64 rows x 16 x 16B)
    {
#pragma unroll
        for (int r = 0; r < 4; r++) {
            int idx = t + r * 256;
            int row = idx >> 4, cq = idx & 15;
            cp_async16(sb + OFF_BB + (uint32_t)(row * BPITCH * 4 + cq * 16),
                       hT + (size_t)row * COUT_ + cq * 4);
        }
        CP_COMMIT();
    }

    for (int jt = 0; jt < 32; jt++) {
        const int j0 = jt * 64;
        const float* Bt = Bbuf + (jt & 1) * BUF_FL;

        CP_WAIT0();
        __syncthreads();      // buf[jt&1] visible; all warps done with jt-1

        // cp.async for jt+1 into the other buffer
        if (jt + 1 < 32) {
            const int j0n = j0 + 64;
            const uint32_t bufn = sb + OFF_BB + (uint32_t)((jt + 1) & 1) * (BUF_FL * 4);
#pragma unroll
            for (int r = 0; r < 4; r++) {
                int idx = t + r * 256;
                int row = idx >> 4, cq = idx & 15;
                cp_async16(bufn + (uint32_t)(row * BPITCH * 4 + cq * 16),
                           hT + (size_t)(j0n + row) * COUT_ + cq * 4);
            }
            CP_COMMIT();
        }

        uint2 bitsA = *(const uint2*)&bpr0[jt * 2];
        uint2 bitsB = *(const uint2*)&bpr1[jt * 2];

#pragma unroll
        for (int ks = 0; ks < 8; ks++) {          // 8 x k8 steps over 64 j
            const int jl = ks * 8 + la;           // local j of a0/a1
            float f1x = b1f[j0 + jl],     f2x = b2f[j0 + jl];
            float f1y = b1f[j0 + jl + 4], f2y = b2f[j0 + jl + 4];
            unsigned wrd0 = (ks < 4) ? bitsA.x : bitsA.y;
            unsigned wrd1 = (ks < 4) ? bitsB.x : bitsB.y;
            const int sh = (ks & 3) * 8 + la;

            float wa0 = wfun(A1_0, A2_0, f1x, f2x, (wrd0 >> sh) & 1u);
            float wa2 = wfun(A1_0, A2_0, f1y, f2y, (wrd0 >> (sh + 4)) & 1u);
            float wb0 = wfun(A1_1, A2_1, f1x, f2x, (wrd1 >> sh) & 1u);
            float wb2 = wfun(A1_1, A2_1, f1y, f2y, (wrd1 >> (sh + 4)) & 1u);
            lsum0 += wa0 + wa2;
            lsum1 += wb0 + wb2;

            uint32_t afr[4];
            afr[0] = to_tf32(wa0);   // (r0, k=la)
            afr[1] = to_tf32(wb0);   // (r1, k=la)
            afr[2] = to_tf32(wa2);   // (r0, k=la+4)
            afr[3] = to_tf32(wb2);   // (r1, k=la+4)

            const float* Brow0 = Bt + (ks * 8 + la) * BPITCH + gn;       // k=la
            const float* Brow1 = Brow0 + 4 * BPITCH;                     // k=la+4
#pragma unroll
            for (int q = 0; q < 8; q++) {
                uint32_t bf0 = __float_as_uint(Brow0[q * 8]);
                uint32_t bf1 = __float_as_uint(Brow1[q * 8]);
                mma_tf32(acc[q], afr, bf0, bf1);
            }
        }
    }

    // row-sum reduce across the 4 lanes sharing each fragment row
    lsum0 += __shfl_xor_sync(0xffffffffu, lsum0, 1);
    lsum0 += __shfl_xor_sync(0xffffffffu, lsum0, 2);
    lsum1 += __shfl_xor_sync(0xffffffffu, lsum1, 1);
    lsum1 += __shfl_xor_sync(0xffffffffu, lsum1, 2);
    if (la == 0) {
        wsum_s[r0loc] = lsum0;
        wsum_s[r1loc] = lsum1;
    }
    __syncthreads();

    // ---- epilogue (C layout of m16n8k8 == m16n8k16) ----
    const float inv0 = 1.f / wsum_s[r0loc];
    const float inv1 = 1.f / wsum_s[r1loc];
    float* op0 = out + ((size_t)(b * N_ + i0 + r0loc)) * (H_ * COUT_) + h * COUT_;
    float* op1 = out + ((size_t)(b * N_ + i0 + r1loc)) * (H_ * COUT_) + h * COUT_;
#pragma unroll
    for (int q = 0; q < 8; q++) {
        int col = q * 8 + la * 2;
        float bx = bias_s[col], by = bias_s[col + 1];
        float2 o0, o1;
        o0.x = fmaxf(acc[q][0] * inv0 + bx, 0.f);
        o0.y = fmaxf(acc[q][1] * inv0 + by, 0.f);
        o1.x = fmaxf(acc[q][2] * inv1 + bx, 0.f);
        o1.y = fmaxf(acc[q][3] * inv1 + by, 0.f);
        *(float2*)&op0[col] = o0;
        *(float2*)&op1[col] = o1;
    }
}

// ---------------------------------------------------------------------------
extern "C" void kernel_launch(void* const* d_in, const int* in_sizes, int n_in,
                              void* d_out, int out_size) {
    const float* x    = (const float*)d_in[0];
    const int*   adj  = (const int*)  d_in[1];
    const float* W    = (const float*)d_in[2];
    const float* a    = (const float*)d_in[3];
    const float* bias = (const float*)d_in[4];
    float* out = (float*)d_out;

    cudaFuncSetAttribute(attn_av_mma, cudaFuncAttributeMaxDynamicSharedMemorySize,
                         SMEM_TOTAL);

    adj_bits_k<<<(B_ * N_) / 8, 256>>>(adj);

    dim3 g1(N_ / 64, H_, B_);
    gemm_hidden<<<g1, 256>>>(x, W, a);

    row_factors<<<B_ * H_, 256>>>();

    dim3 g4(N_ / 128, H_, B_);
    attn_av_mma<<<g4, 256, SMEM_TOTAL>>>(bias, out);
}

// round 14
// speedup vs baseline: 2.0877x; 1.2187x over previous
#include <cuda_runtime.h>
#include <cuda_bf16.h>
#include <cstdint>

#define B_    4
#define N_    2048
#define CIN_  256
#define COUT_ 64
#define H_    8
#define ALPHA 0.2f

// ---------------- scratch (__device__ globals; no allocs allowed) -----------
__device__ float g_htf[(size_t)B_ * H_ * N_ * COUT_];   // hidden, tf32-rounded f32
__device__ float g_s1[B_ * H_ * N_];
__device__ float g_s2[B_ * H_ * N_];
__device__ float g_A1[B_ * H_ * N_];    // exp(s1 - M)
__device__ float g_A2[B_ * H_ * N_];    // exp(0.2 s1 - M)
__device__ float g_B1[B_ * H_ * N_];    // exp(s2)
__device__ float g_B2[B_ * H_ * N_];    // exp(0.2 s2)
__device__ unsigned g_bits[(size_t)B_ * N_ * (N_ / 32)];          // adj bitmask

// ---------------- helpers (sm_80-era PTX only) ------------------------------
__device__ __forceinline__ uint32_t smem_u32(const void* p) {
    uint32_t a;
    asm("{ .reg .u64 t; cvta.to.shared.u64 t, %1; cvt.u32.u64 %0, t; }"
        : "=r"(a) : "l"(p));
    return a;
}
__device__ __forceinline__ uint32_t to_tf32(float x) {
    uint32_t r;
    asm("cvt.rna.tf32.f32 %0, %1;" : "=r"(r) : "f"(x));
    return r;
}
__device__ __forceinline__ void mma_tf32(float* c, const uint32_t* a,
                                         uint32_t b0, uint32_t b1) {
    asm volatile("mma.sync.aligned.m16n8k8.row.col.f32.tf32.tf32.f32 "
                 "{%0,%1,%2,%3}, {%4,%5,%6,%7}, {%8,%9}, {%0,%1,%2,%3};"
                 : "+f"(c[0]), "+f"(c[1]), "+f"(c[2]), "+f"(c[3])
                 : "r"(a[0]), "r"(a[1]), "r"(a[2]), "r"(a[3]), "r"(b0), "r"(b1));
}
__device__ __forceinline__ void cp_async16(uint32_t dst, const void* src) {
    asm volatile("cp.async.cg.shared.global [%0], [%1], 16;"
                 :: "r"(dst), "l"(src) : "memory");
}
#define CP_COMMIT() asm volatile("cp.async.commit_group;" ::: "memory")
#define CP_WAIT0()  asm volatile("cp.async.wait_group 0;" ::: "memory")

// weight: exp(leaky(s1+s2)-M) = max(A1*B1, A2*B2)
__device__ __forceinline__ float wfun(float A1, float A2,
                                      float f1, float f2, unsigned bit) {
    float w = fmaxf(A1 * f1, A2 * f2);
    return bit ? w : 0.f;
}

// ---------------------------------------------------------------------------
// Kernel 1 (tf32 MMA): hidden = x @ W^T, fused s1/s2 scores.
// CTA = 64 rows x 4 heads (256 couts); 8 warps: warp = (head, 32-row half).
// K in 8 chunks of 32; tiles tf32-converted at staging, pitch 36 (STS.128-
// aligned; A/B fragment LDS conflict-free: bank = 4*row + la).
// ---------------------------------------------------------------------------
#define GP 36

__global__ void __launch_bounds__(256) gemm_hidden_tc(const float* __restrict__ x,
                                                      const float* __restrict__ Wf,
                                                      const float* __restrict__ av) {
    __shared__ uint32_t xs[64 * GP];      //  9.2 KB
    __shared__ uint32_t ws[256 * GP];     // 36.9 KB
    __shared__ float a1s[256], a2s[256];  //  2.0 KB  (total 48.1 KB static)

    const int b  = blockIdx.z;
    const int yg = blockIdx.y;            // head group: heads 4yg..4yg+3
    const int m0 = blockIdx.x * 64;
    const int t = threadIdx.x, wid = t >> 5, lane = t & 31;
    const int la = lane & 3, gq = lane >> 2;
    const int hg  = wid >> 1;             // local head 0..3
    const int head = yg * 4 + hg;
    const int mt0 = (wid & 1) * 32;       // warp's 32-row half

    // a vectors for the 4 heads of this group
    {
        int hl = t >> 6, c = t & 63;
        a1s[t] = av[(yg * 4 + hl) * 128 + c];
        a2s[t] = av[(yg * 4 + hl) * 128 + 64 + c];
    }

    const float* xb = x + (size_t)b * N_ * CIN_;
    float acc[2][8][4] = {};

    for (int k0 = 0; k0 < CIN_; k0 += 32) {
        // stage x tile [64][32] -> tf32
#pragma unroll
        for (int r = 0; r < 2; r++) {
            int f = t + r * 256;
            int row = f >> 3, c4 = (f & 7) * 4;
            float4 v = *(const float4*)&xb[(size_t)(m0 + row) * CIN_ + k0 + c4];
            uint4 u = make_uint4(to_tf32(v.x), to_tf32(v.y), to_tf32(v.z), to_tf32(v.w));
            *(uint4*)&xs[row * GP + c4] = u;
        }
        // stage W tile [256][32] -> tf32 (global cout rows yg*256..+255)
#pragma unroll
        for (int r = 0; r < 8; r++) {
            int f = t + r * 256;
            int row = f >> 3, c4 = (f & 7) * 4;
            float4 w = *(const float4*)&Wf[(size_t)(yg * 256 + row) * CIN_ + k0 + c4];
            uint4 u = make_uint4(to_tf32(w.x), to_tf32(w.y), to_tf32(w.z), to_tf32(w.w));
            *(uint4*)&ws[row * GP + c4] = u;
        }
        __syncthreads();

#pragma unroll
        for (int ks = 0; ks < 4; ks++) {
            const int kk = ks * 8;
            uint32_t af[2][4];
#pragma unroll
            for (int mt = 0; mt < 2; mt++) {
                int br = mt0 + mt * 16 + gq;
                af[mt][0] = xs[br * GP + kk + la];
                af[mt][1] = xs[(br + 8) * GP + kk + la];
                af[mt][2] = xs[br * GP + kk + la + 4];
                af[mt][3] = xs[(br + 8) * GP + kk + la + 4];
            }
#pragma unroll
            for (int q = 0; q < 8; q++) {
                int n = hg * 64 + q * 8 + gq;
                uint32_t b0 = ws[n * GP + kk + la];
                uint32_t b1 = ws[n * GP + kk + la + 4];
                mma_tf32(acc[0][q], af[0], b0, b1);
                mma_tf32(acc[1][q], af[1], b0, b1);
            }
        }
        __syncthreads();
    }

    // epilogue: hidden (tf32-rounded) + fused scores
    const int bh = b * H_ + head;
    const size_t obase = (size_t)bh * N_ * COUT_;
    float p1[4] = {0.f, 0.f, 0.f, 0.f};
    float p2[4] = {0.f, 0.f, 0.f, 0.f};
#pragma unroll
    for (int mt = 0; mt < 2; mt++) {
        int r0 = mt0 + mt * 16 + gq;
#pragma unroll
        for (int q = 0; q < 8; q++) {
            int col = q * 8 + la * 2;
            float a1x = a1s[hg * 64 + col], a1y = a1s[hg * 64 + col + 1];
            float a2x = a2s[hg * 64 + col], a2y = a2s[hg * 64 + col + 1];
            p1[mt * 2 + 0] += acc[mt][q][0] * a1x + acc[mt][q][1] * a1y;
            p2[mt * 2 + 0] += acc[mt][q][0] * a2x + acc[mt][q][1] * a2y;
            p1[mt * 2 + 1] += acc[mt][q][2] * a1x + acc[mt][q][3] * a1y;
            p2[mt * 2 + 1] += acc[mt][q][2] * a2x + acc[mt][q][3] * a2y;
            float2 h0, h1;
            h0.x = __uint_as_float(to_tf32(acc[mt][q][0]));
            h0.y = __uint_as_float(to_tf32(acc[mt][q][1]));
            h1.x = __uint_as_float(to_tf32(acc[mt][q][2]));
            h1.y = __uint_as_float(to_tf32(acc[mt][q][3]));
            *(float2*)&g_htf[obase + (size_t)(m0 + r0) * COUT_ + col] = h0;
            *(float2*)&g_htf[obase + (size_t)(m0 + r0 + 8) * COUT_ + col] = h1;
        }
    }
#pragma unroll
    for (int off = 1; off <= 2; off <<= 1) {
#pragma unroll
        for (int i = 0; i < 4; i++) {
            p1[i] += __shfl_xor_sync(0xffffffffu, p1[i], off);
            p2[i] += __shfl_xor_sync(0xffffffffu, p2[i], off);
        }
    }
    if (la == 0) {
#pragma unroll
        for (int mt = 0; mt < 2; mt++) {
#pragma unroll
            for (int hf = 0; hf < 2; hf++) {
                int r = mt0 + mt * 16 + hf * 8 + gq;
                g_s1[bh * N_ + m0 + r] = p1[mt * 2 + hf];
                g_s2[bh * N_ + m0 + r] = p2[mt * 2 + hf];
            }
        }
    }
}

// ---------------------------------------------------------------------------
// Kernel 2: per (b,h): s2max reduce + factor precompute
// ---------------------------------------------------------------------------
__global__ void row_factors() {
    __shared__ float red[256];
    __shared__ float s2max_s;
    int bh = blockIdx.x;
    const float* s1 = g_s1 + bh * N_;
    const float* s2 = g_s2 + bh * N_;
    float m = -1e30f;
    for (int j = threadIdx.x; j < N_; j += 256) m = fmaxf(m, s2[j]);
    red[threadIdx.x] = m;
    __syncthreads();
    for (int s = 128; s > 0; s >>= 1) {
        if (threadIdx.x < s) red[threadIdx.x] = fmaxf(red[threadIdx.x], red[threadIdx.x + s]);
        __syncthreads();
    }
    if (threadIdx.x == 0) s2max_s = red[0];
    __syncthreads();
    const float s2m = s2max_s;
    for (int j = threadIdx.x; j < N_; j += 256) {
        float s1v = s1[j], s2v = s2[j];
        float e = s1v + s2m;
        float M = (e >= 0.f) ? e : ALPHA * e;
        g_A1[bh * N_ + j] = __expf(s1v - M);
        g_A2[bh * N_ + j] = __expf(ALPHA * s1v - M);
        g_B1[bh * N_ + j] = __expf(s2v);
        g_B2[bh * N_ + j] = __expf(ALPHA * s2v);
    }
}

// ---------------------------------------------------------------------------
// Kernel 3: adj -> bitmask, 4 words per loop iteration (MLP 4)
// ---------------------------------------------------------------------------
__global__ void adj_bits_k(const int* __restrict__ adj) {
    int wid  = threadIdx.x >> 5, lane = threadIdx.x & 31;
    int row  = blockIdx.x * 8 + wid;
    const int* ap = adj + (size_t)row * N_;
    unsigned* bp  = g_bits + (size_t)row * (N_ / 32);
#pragma unroll 4
    for (int w2 = 0; w2 < N_ / 128; w2++) {
        int v0 = ap[w2 * 128 + lane];
        int v1 = ap[w2 * 128 + 32 + lane];
        int v2 = ap[w2 * 128 + 64 + lane];
        int v3 = ap[w2 * 128 + 96 + lane];
        unsigned m0 = __ballot_sync(0xffffffffu, v0 > 0);
        unsigned m1 = __ballot_sync(0xffffffffu, v1 > 0);
        unsigned m2 = __ballot_sync(0xffffffffu, v2 > 0);
        unsigned m3 = __ballot_sync(0xffffffffu, v3 > 0);
        if (lane == 0) {
            bp[w2 * 4 + 0] = m0; bp[w2 * 4 + 1] = m1;
            bp[w2 * 4 + 2] = m2; bp[w2 * 4 + 3] = m3;
        }
    }
}

// ---------------------------------------------------------------------------
// Kernel 4 (round-12 proven): single-term tf32 MMA AV, register A-fragments,
// B f32 double-buffered (pitch 72), 1 sync per tile.
// ---------------------------------------------------------------------------
#define BPITCH   72
#define BUF_FL   (64 * BPITCH)
#define OFF_BB   0
#define OFF_B1F  36864
#define OFF_B2F  45056
#define OFF_WSUM 53248
#define OFF_BIAS 53760
#define SMEM_TOTAL 54016

__global__ void __launch_bounds__(256) attn_av_mma(const float* __restrict__ bias,
                                                   float* __restrict__ out) {
    extern __shared__ char smem[];
    const uint32_t sb = smem_u32(smem);
    const int b = blockIdx.z, h = blockIdx.y, i0 = blockIdx.x * 128;
    const int bh = b * H_ + h;
    const int t = threadIdx.x, wid = t >> 5, lane = t & 31;

    float* wsum_s = (float*)(smem + OFF_WSUM);
    float* b1f    = (float*)(smem + OFF_B1F);
    float* b2f    = (float*)(smem + OFF_B2F);
    float* bias_s = (float*)(smem + OFF_BIAS);
    float* Bbuf   = (float*)(smem + OFF_BB);
    if (t < 16) *(float4*)&bias_s[t * 4] = *(const float4*)&bias[h * COUT_ + t * 4];

    // prologue: stage factor arrays (visible after first loop sync)
    {
        const float* B1g = g_B1 + bh * N_;
        const float* B2g = g_B2 + bh * N_;
#pragma unroll
        for (int r = 0; r < 2; r++) {
            int q = (t + r * 256) * 4;
            *(float4*)&b1f[q] = *(const float4*)&B1g[q];
            *(float4*)&b2f[q] = *(const float4*)&B2g[q];
        }
    }

    const int m0 = wid * 16;
    const int r0loc = m0 + (lane >> 2);
    const int r1loc = r0loc + 8;
    const int la = lane & 3;
    const int gn = lane >> 2;
    const float A1_0 = g_A1[bh * N_ + i0 + r0loc];
    const float A2_0 = g_A2[bh * N_ + i0 + r0loc];
    const float A1_1 = g_A1[bh * N_ + i0 + r1loc];
    const float A2_1 = g_A2[bh * N_ + i0 + r1loc];
    float lsum0 = 0.f, lsum1 = 0.f;

    const float* hT = g_htf + (size_t)bh * N_ * COUT_;
    const unsigned* bpr0 = g_bits + ((size_t)(b * N_ + i0 + r0loc)) * (N_ / 32);
    const unsigned* bpr1 = g_bits + ((size_t)(b * N_ + i0 + r1loc)) * (N_ / 32);

    float acc[8][4] = {};

    // stage jt=0 into buffer 0
    {
#pragma unroll
        for (int r = 0; r < 4; r++) {
            int idx = t + r * 256;
            int row = idx >> 4, cq = idx & 15;
            cp_async16(sb + OFF_BB + (uint32_t)(row * BPITCH * 4 + cq * 16),
                       hT + (size_t)row * COUT_ + cq * 4);
        }
        CP_COMMIT();
    }

    for (int jt = 0; jt < 32; jt++) {
        const int j0 = jt * 64;
        const float* Bt = Bbuf + (jt & 1) * BUF_FL;

        CP_WAIT0();
        __syncthreads();

        if (jt + 1 < 32) {
            const int j0n = j0 + 64;
            const uint32_t bufn = sb + OFF_BB + (uint32_t)((jt + 1) & 1) * (BUF_FL * 4);
#pragma unroll
            for (int r = 0; r < 4; r++) {
                int idx = t + r * 256;
                int row = idx >> 4, cq = idx & 15;
                cp_async16(bufn + (uint32_t)(row * BPITCH * 4 + cq * 16),
                           hT + (size_t)(j0n + row) * COUT_ + cq * 4);
            }
            CP_COMMIT();
        }

        uint2 bitsA = *(const uint2*)&bpr0[jt * 2];
        uint2 bitsB = *(const uint2*)&bpr1[jt * 2];

#pragma unroll
        for (int ks = 0; ks < 8; ks++) {
            const int jl = ks * 8 + la;
            float f1x = b1f[j0 + jl],     f2x = b2f[j0 + jl];
            float f1y = b1f[j0 + jl + 4], f2y = b2f[j0 + jl + 4];
            unsigned wrd0 = (ks < 4) ? bitsA.x : bitsA.y;
            unsigned wrd1 = (ks < 4) ? bitsB.x : bitsB.y;
            const int sh = (ks & 3) * 8 + la;

            float wa0 = wfun(A1_0, A2_0, f1x, f2x, (wrd0 >> sh) & 1u);
            float wa2 = wfun(A1_0, A2_0, f1y, f2y, (wrd0 >> (sh + 4)) & 1u);
            float wb0 = wfun(A1_1, A2_1, f1x, f2x, (wrd1 >> sh) & 1u);
            float wb2 = wfun(A1_1, A2_1, f1y, f2y, (wrd1 >> (sh + 4)) & 1u);
            lsum0 += wa0 + wa2;
            lsum1 += wb0 + wb2;

            uint32_t afr[4];
            afr[0] = to_tf32(wa0);
            afr[1] = to_tf32(wb0);
            afr[2] = to_tf32(wa2);
            afr[3] = to_tf32(wb2);

            const float* Brow0 = Bt + (ks * 8 + la) * BPITCH + gn;
            const float* Brow1 = Brow0 + 4 * BPITCH;
#pragma unroll
            for (int q = 0; q < 8; q++) {
                uint32_t bf0 = __float_as_uint(Brow0[q * 8]);
                uint32_t bf1 = __float_as_uint(Brow1[q * 8]);
                mma_tf32(acc[q], afr, bf0, bf1);
            }
        }
    }

    lsum0 += __shfl_xor_sync(0xffffffffu, lsum0, 1);
    lsum0 += __shfl_xor_sync(0xffffffffu, lsum0, 2);
    lsum1 += __shfl_xor_sync(0xffffffffu, lsum1, 1);
    lsum1 += __shfl_xor_sync(0xffffffffu, lsum1, 2);
    if (la == 0) {
        wsum_s[r0loc] = lsum0;
        wsum_s[r1loc] = lsum1;
    }
    __syncthreads();

    const float inv0 = 1.f / wsum_s[r0loc];
    const float inv1 = 1.f / wsum_s[r1loc];
    float* op0 = out + ((size_t)(b * N_ + i0 + r0loc)) * (H_ * COUT_) + h * COUT_;
    float* op1 = out + ((size_t)(b * N_ + i0 + r1loc)) * (H_ * COUT_) + h * COUT_;
#pragma unroll
    for (int q = 0; q < 8; q++) {
        int col = q * 8 + la * 2;
        float bx = bias_s[col], by = bias_s[col + 1];
        float2 o0, o1;
        o0.x = fmaxf(acc[q][0] * inv0 + bx, 0.f);
        o0.y = fmaxf(acc[q][1] * inv0 + by, 0.f);
        o1.x = fmaxf(acc[q][2] * inv1 + bx, 0.f);
        o1.y = fmaxf(acc[q][3] * inv1 + by, 0.f);
        *(float2*)&op0[col] = o0;
        *(float2*)&op1[col] = o1;
    }
}

// ---------------------------------------------------------------------------
extern "C" void kernel_launch(void* const* d_in, const int* in_sizes, int n_in,
                              void* d_out, int out_size) {
    const float* x    = (const float*)d_in[0];
    const int*   adj  = (const int*)  d_in[1];
    const float* W    = (const float*)d_in[2];
    const float* a    = (const float*)d_in[3];
    const float* bias = (const float*)d_in[4];
    float* out = (float*)d_out;

    cudaFuncSetAttribute(attn_av_mma, cudaFuncAttributeMaxDynamicSharedMemorySize,
                         SMEM_TOTAL);

    adj_bits_k<<<(B_ * N_) / 8, 256>>>(adj);

    dim3 g1(N_ / 64, 2, B_);
    gemm_hidden_tc<<<g1, 256>>>(x, W, a);

    row_factors<<<B_ * H_, 256>>>();

    dim3 g4(N_ / 128, H_, B_);
    attn_av_mma<<<g4, 256, SMEM_TOTAL>>>(bias, out);
}